// round 11
// baseline (speedup 1.0000x reference)
#include <cuda_runtime.h>
#include <cuda_fp16.h>
#include <cstdint>

#define BB 2
#define SS 3144
#define CC 256
#define HH 8
#define HD 32
#define QN 8
#define MTOT (BB*SS)            /* 6288 */
#define SCALE 0.1767766952966369f
#define KSCALE (0.1767766952966369f * 1.44269504f)   /* SCALE * log2(e) */
#define LN2 0.6931471805599453f
#define NKT2 ((SS + 63) / 64)   /* 50 key tiles of 64 */
#define NQT64 ((SS + 63) / 64)  /* 50 query tiles of 64 */
#define NM ((size_t)BB*SS*SS)

typedef unsigned long long u64;
typedef unsigned int u32;
typedef unsigned short u16;

__device__ __align__(16) __half d_qh[BB*HH*SS*HD];  // head-major fp16
__device__ __align__(16) __half d_kh[BB*HH*SS*HD];  // scaled by KSCALE (K and V)
__device__ __align__(16) float  d_v[BB*SS*CC];
__device__ __align__(16) float  d_acc[BB*SS*CC];    // attention out (f32)
__device__ __align__(16) __half d_m16[BB*SS*SS];    // (mask + 1e-6) in fp16
__device__ __align__(16) __half d_wh[768*CC];       // [wq;wk;wv] split
__device__ __align__(16) __half d_wl[768*CC];
__device__ __align__(16) __half d_woh[CC*CC];       // wo split
__device__ __align__(16) __half d_wol[CC*CC];
__device__ __align__(16) __half d_acch[BB*SS*CC];   // acc(+lepe) split
__device__ __align__(16) __half d_accl[BB*SS*CC];

// ---------------- helpers ----------------
__device__ __forceinline__ u32 smem_u32(const void* p) {
    u32 a;
    asm("{ .reg .u64 t; cvta.to.shared.u64 t, %1; cvt.u32.u64 %0, t; }" : "=r"(a) : "l"(p));
    return a;
}
__device__ __forceinline__ u32 pack_h2(float lo, float hi) {
    u32 r; asm("cvt.rn.f16x2.f32 %0, %1, %2;" : "=r"(r) : "f"(hi), "f"(lo)); return r;
}
__device__ __forceinline__ float ex2f(float x) {
    float r; asm("ex2.approx.f32 %0, %1;" : "=f"(r) : "f"(x)); return r;
}
__device__ __forceinline__ void ldx4(u32* r, u32 saddr) {
    asm volatile("ldmatrix.sync.aligned.m8n8.x4.shared.b16 {%0,%1,%2,%3}, [%4];"
                 : "=r"(r[0]), "=r"(r[1]), "=r"(r[2]), "=r"(r[3]) : "r"(saddr));
}
__device__ __forceinline__ void ldx4t(u32* r, u32 saddr) {
    asm volatile("ldmatrix.sync.aligned.m8n8.x4.trans.shared.b16 {%0,%1,%2,%3}, [%4];"
                 : "=r"(r[0]), "=r"(r[1]), "=r"(r[2]), "=r"(r[3]) : "r"(saddr));
}
__device__ __forceinline__ void mma_h(float* c, const u32* a, u32 b0, u32 b1) {
    asm volatile("mma.sync.aligned.m16n8k16.row.col.f32.f16.f16.f32 "
                 "{%0,%1,%2,%3}, {%4,%5,%6,%7}, {%8,%9}, {%0,%1,%2,%3};"
                 : "+f"(c[0]), "+f"(c[1]), "+f"(c[2]), "+f"(c[3])
                 : "r"(a[0]), "r"(a[1]), "r"(a[2]), "r"(a[3]), "r"(b0), "r"(b1));
}
__device__ __forceinline__ void split_h(float v, __half &h, __half &l) {
    h = __float2half_rn(v);
    l = __float2half_rn(v - __half2float(h));
}

// ---------------------------------------------------------------------------
// Kernel 0a: split [wq;wk;wv], wo into fp16 hi/lo (weights only)
// ---------------------------------------------------------------------------
__global__ __launch_bounds__(256) void cvt_kernel(
    const float* __restrict__ wq, const float* __restrict__ wk,
    const float* __restrict__ wv, const float* __restrict__ wo)
{
    int j = blockIdx.x * 256 + threadIdx.x;      // 0 .. 4*65536-1
    int sec = j >> 16, off = j & 65535;
    const float* src = (sec == 0) ? wq : (sec == 1) ? wk : (sec == 2) ? wv : wo;
    __half h, l; split_h(src[off], h, l);
    if (sec < 3) { d_wh[j] = h; d_wl[j] = l; }
    else         { d_woh[off] = h; d_wol[off] = l; }
}

// ---------------------------------------------------------------------------
// Kernel 0b: mask -> fp16 with +1e-6 folded in
// ---------------------------------------------------------------------------
__global__ __launch_bounds__(256) void mask16_kernel(const float* __restrict__ m)
{
    size_t i = ((size_t)blockIdx.x * 256 + threadIdx.x) * 8;
    if (i >= NM) return;
    float4 a = *(const float4*)(m + i);
    float4 b = *(const float4*)(m + i + 4);
    __half hh[8];
    hh[0] = __float2half_rn(a.x + 1e-6f);
    hh[1] = __float2half_rn(a.y + 1e-6f);
    hh[2] = __float2half_rn(a.z + 1e-6f);
    hh[3] = __float2half_rn(a.w + 1e-6f);
    hh[4] = __float2half_rn(b.x + 1e-6f);
    hh[5] = __float2half_rn(b.y + 1e-6f);
    hh[6] = __float2half_rn(b.z + 1e-6f);
    hh[7] = __float2half_rn(b.w + 1e-6f);
    *(uint4*)&d_m16[i] = *(uint4*)hh;
}

// ---------------------------------------------------------------------------
// Kernel 1: fused QKV projection. x split in-kernel.
// q,k sections: single-pass fp16 HMMA. v section: 3-pass split-fp16.
// ---------------------------------------------------------------------------
__global__ __launch_bounds__(256) void qkv_kernel(
    const float* __restrict__ x,
    const float* __restrict__ bq, const float* __restrict__ bk,
    const float* __restrict__ bv)
{
    __shared__ __align__(16) u16 Xh[64*40];
    __shared__ __align__(16) u16 Xl[64*40];
    __shared__ __align__(16) u16 Wh[64*40];
    __shared__ __align__(16) u16 Wl[64*40];

    const int m0 = blockIdx.x * 64;
    const int n0 = blockIdx.y * 64;       // global 0..767
    const int t = threadIdx.x;
    const int w = t >> 5, lane = t & 31;
    const int g = lane >> 2, t4 = lane & 3;
    const int wr = w >> 1, wc = w & 1;
    const int sec = n0 >> 8;
    const int nbase = n0 & 255;
    const bool isv = (sec == 2);

    float acc[4][4];
    #pragma unroll
    for (int i = 0; i < 4; i++)
        #pragma unroll
        for (int c = 0; c < 4; c++) acc[i][c] = 0.f;

    const u32 xb  = smem_u32(Xh), xlb = smem_u32(Xl);
    const u32 wb  = smem_u32(Wh), wlb = smem_u32(Wl);

    for (int kk = 0; kk < CC; kk += 32) {
        __syncthreads();
        {
            int r = t >> 2, c8 = (t & 3) * 8;
            int gm = m0 + r;
            float4 f0 = make_float4(0.f,0.f,0.f,0.f), f1 = f0;
            if (gm < MTOT) {
                f0 = *(const float4*)(x + (size_t)gm*CC + kk + c8);
                f1 = *(const float4*)(x + (size_t)gm*CC + kk + c8 + 4);
            }
            float vv[8] = {f0.x,f0.y,f0.z,f0.w,f1.x,f1.y,f1.z,f1.w};
            __half hh[8], ll[8];
            #pragma unroll
            for (int i = 0; i < 8; i++) split_h(vv[i], hh[i], ll[i]);
            *(uint4*)&Xh[r*40 + c8] = *(uint4*)hh;
            if (isv) *(uint4*)&Xl[r*40 + c8] = *(uint4*)ll;
            int wrow = n0 + r;
            *(uint4*)&Wh[r*40 + c8] = *(const uint4*)&d_wh[(size_t)wrow*CC + kk + c8];
            if (isv) *(uint4*)&Wl[r*40 + c8] = *(const uint4*)&d_wl[(size_t)wrow*CC + kk + c8];
        }
        __syncthreads();

        u32 ax[2][4], al[2][4];
        #pragma unroll
        for (int ks = 0; ks < 2; ks++) {
            u32 aoff = (u32)(((16*wr + (lane & 15))*40 + ks*16 + ((lane>>4)&1)*8) * 2);
            ldx4(ax[ks], xb + aoff);
            if (isv) ldx4(al[ks], xlb + aoff);
        }
        #pragma unroll
        for (int ks = 0; ks < 2; ks++) {
            #pragma unroll
            for (int np = 0; np < 2; np++) {
                u32 boff = (u32)(((32*wc + np*16 + ((lane>>4)&1)*8 + (lane & 7))*40
                                  + ks*16 + ((lane>>3)&1)*8) * 2);
                u32 bh4[4];
                ldx4(bh4, wb + boff);
                mma_h(acc[2*np],   ax[ks], bh4[0], bh4[1]);
                mma_h(acc[2*np+1], ax[ks], bh4[2], bh4[3]);
                if (isv) {
                    u32 bl4[4];
                    ldx4(bl4, wlb + boff);
                    mma_h(acc[2*np],   ax[ks], bl4[0], bl4[1]);
                    mma_h(acc[2*np],   al[ks], bh4[0], bh4[1]);
                    mma_h(acc[2*np+1], ax[ks], bl4[2], bl4[3]);
                    mma_h(acc[2*np+1], al[ks], bh4[2], bh4[3]);
                }
            }
        }
    }

    const float* bsec = (sec == 0) ? bq : (sec == 1) ? bk : bv;
    #pragma unroll
    for (int nt = 0; nt < 4; nt++) {
        int ct = 32*wc + 8*nt + 2*t4;
        int c = nbase + ct;
        float b0v = bsec[c], b1v = bsec[c+1];
        #pragma unroll
        for (int rr = 0; rr < 2; rr++) {
            int gm = m0 + 16*wr + g + rr*8;
            if (gm >= MTOT) continue;
            float v0 = acc[nt][2*rr]   + b0v;
            float v1 = acc[nt][2*rr+1] + b1v;
            int b = gm / SS, srow = gm % SS;
            if (sec == 0) {
                *(__half2*)&d_qh[(((size_t)b*HH + (c>>5))*SS + srow)*HD + (c&31)] =
                    __floats2half2_rn(v0, v1);
            } else if (sec == 1) {
                *(__half2*)&d_kh[(((size_t)b*HH + (c>>5))*SS + srow)*HD + (c&31)] =
                    __floats2half2_rn(v0*KSCALE, v1*KSCALE);
            } else {
                *(float2*)&d_v[(size_t)gm*CC + c] = make_float2(v0, v1);
            }
        }
    }
}

// ---------------------------------------------------------------------------
// Kernel 2: fp16 mma.sync attention — 2 heads per block, fp32 accumulators.
// K pre-scaled by SCALE*log2e; w = m16 * ex2(s); final /= rowsum, * ln2.
// __launch_bounds__(256, 4): force 64 regs -> 4 blocks/SM (occupancy lever).
// ---------------------------------------------------------------------------
__global__ void __launch_bounds__(256, 4) attn_mma_kernel()
{
    __shared__ __align__(16) u16 Qsm[2*64*40];     // 10240 B (2 heads)
    __shared__ __align__(16) u16 Ksm[2*2*64*40];   // 20480 B (2 heads x double buf)

    const int t = threadIdx.x;
    const int w = t >> 5, lane = t & 31;
    const int g = lane >> 2, t4 = lane & 3;
    const int hp = w >> 2, w4 = w & 3;
    const int bhp = blockIdx.x;
    const int b = bhp >> 2, hpair = bhp & 3;
    const int h = hpair*2 + hp;
    const int q0 = blockIdx.y * 64;

    // ---- stage Q tiles for both heads ----
    {
        int hld = t >> 7, r = (t >> 1) & 63, part = t & 1;
        const __half* qb2 = d_qh + (((size_t)b*HH + hpair*2 + hld) * SS) * HD;
        int gq = q0 + r;
        uint4 a0 = make_uint4(0u,0u,0u,0u), a1 = make_uint4(0u,0u,0u,0u);
        if (gq < SS) {
            a0 = *(const uint4*)(qb2 + (size_t)gq*HD + part*16);
            a1 = *(const uint4*)(qb2 + (size_t)gq*HD + part*16 + 8);
        }
        *(uint4*)&Qsm[hld*64*40 + r*40 + part*16]     = a0;
        *(uint4*)&Qsm[hld*64*40 + r*40 + part*16 + 8] = a1;
    }
    __syncthreads();

    u32 qa[2][4];
    {
        u32 qs = smem_u32(Qsm) + (u32)(hp*64*40*2);
        int row = 16*w4 + (lane & 15);
        int cb = (lane >> 4) * 8;
        ldx4(qa[0], qs + (u32)((row*40 + cb) * 2));
        ldx4(qa[1], qs + (u32)((row*40 + cb + 16) * 2));
    }

    const u32 ks_base = smem_u32(Ksm);

    const int r0  = q0 + 16*w4 + g;
    const int r1i = r0 + 8;
    const __half* mbb = d_m16 + (size_t)b * SS * SS;
    const __half* mr0 = (r0  < SS) ? mbb + (size_t)r0  * SS : (const __half*)0;
    const __half* mr1 = (r1i < SS) ? mbb + (size_t)r1i * SS : (const __half*)0;

    float oacc[4][4];
    #pragma unroll
    for (int i = 0; i < 4; i++)
        #pragma unroll
        for (int c = 0; c < 4; c++) oacc[i][c] = 0.f;
    float rs0 = 0.f, rs1 = 0.f;

    // mask prefetch double-buffer (f16x2 pairs)
    u32 mbuf[2][4];
    auto do_pref = [&](int gjdx, u32* dst) {
        int base = gjdx * 16;
        #pragma unroll
        for (int p = 0; p < 2; p++) {
            int gk = base + p*8 + 2*t4;
            u32 v0 = 0u, v1 = 0u;
            if (gk < SS) {
                if (mr0) v0 = *(const u32*)(mr0 + gk);
                if (mr1) v1 = *(const u32*)(mr1 + gk);
            }
            dst[2*p]   = v0;
            dst[2*p+1] = v1;
        }
    };
    do_pref(0, mbuf[0]);

    // K tile load/store: 256 thr cover 2 heads x 64 rows x 32 halves
    const int khld = t >> 7, kkr = (t >> 1) & 63, kpart = t & 1;
    const __half* kldb = d_kh + (((size_t)b*HH + hpair*2 + khld) * SS) * HD;
    auto ldK = [&](int kt, uint4 &a0, uint4 &a1) {
        int gk = kt*64 + kkr;
        a0 = make_uint4(0u,0u,0u,0u); a1 = make_uint4(0u,0u,0u,0u);
        if (gk < SS) {
            a0 = *(const uint4*)(kldb + (size_t)gk*HD + kpart*16);
            a1 = *(const uint4*)(kldb + (size_t)gk*HD + kpart*16 + 8);
        }
    };
    auto stK = [&](int buf, uint4 a0, uint4 a1) {
        int base = (khld*2 + buf)*64*40;
        *(uint4*)&Ksm[base + kkr*40 + kpart*16]     = a0;
        *(uint4*)&Ksm[base + kkr*40 + kpart*16 + 8] = a1;
    };

    {
        uint4 p0, p1;
        ldK(0, p0, p1);
        stK(0, p0, p1);
    }
    __syncthreads();

    for (int kt = 0; kt < NKT2; kt++) {
        const u32 ks = ks_base + (u32)(((hp*2 + (kt & 1)) * 64*40) * 2);
        const bool more = (kt + 1 < NKT2);
        uint4 n0v, n1v;
        if (more) ldK(kt + 1, n0v, n1v);

        #pragma unroll
        for (int j = 0; j < 4; j++) {
            const u32* mc = mbuf[j & 1];
            // ---- QK (fp32 acc) ----
            float sc[2][4];
            #pragma unroll
            for (int p = 0; p < 2; p++) {
                #pragma unroll
                for (int c = 0; c < 4; c++) sc[p][c] = 0.f;
                int nt = 2*j + p;
                u32 br[4];
                ldx4(br, ks + (u32)(((nt*8 + (lane & 7))*40 + ((lane>>3)&3)*8) * 2));
                mma_h(sc[p], qa[0], br[0], br[1]);
                mma_h(sc[p], qa[1], br[2], br[3]);
            }
            // prefetch next chunk's mask
            {
                int gn = kt*4 + j + 1;
                if (gn < NKT2*4) do_pref(gn, mbuf[(j+1) & 1]);
            }
            // ---- epilogue: w = m16 * 2^s  (s already scaled by log2e) ----
            u32 wh[4];
            #pragma unroll
            for (int p = 0; p < 2; p++) {
                float2 m0 = __half22float2(*(const __half2*)&mc[2*p]);
                float2 m1 = __half22float2(*(const __half2*)&mc[2*p+1]);
                float w00 = m0.x * ex2f(sc[p][0]);
                float w01 = m0.y * ex2f(sc[p][1]);
                float w10 = m1.x * ex2f(sc[p][2]);
                float w11 = m1.y * ex2f(sc[p][3]);
                rs0 += w00 + w01;
                rs1 += w10 + w11;
                wh[2*p]   = pack_h2(w00, w01);
                wh[2*p+1] = pack_h2(w10, w11);
            }
            // ---- PV via trans-ldmatrix straight from K tile ----
            #pragma unroll
            for (int ip = 0; ip < 2; ip++) {
                u32 vr[4];
                ldx4t(vr, ks + (u32)(((16*j + ((lane>>3)&1)*8 + (lane & 7))*40
                                      + ((lane>>4)&1)*8 + ip*16) * 2));
                mma_h(oacc[2*ip],   wh, vr[0], vr[1]);
                mma_h(oacc[2*ip+1], wh, vr[2], vr[3]);
            }
        }

        if (more) stK((kt + 1) & 1, n0v, n1v);
        __syncthreads();
    }

    rs0 += __shfl_xor_sync(0xffffffffu, rs0, 1);
    rs0 += __shfl_xor_sync(0xffffffffu, rs0, 2);
    rs1 += __shfl_xor_sync(0xffffffffu, rs1, 1);
    rs1 += __shfl_xor_sync(0xffffffffu, rs1, 2);
    // V carried an extra log2(e) factor (K==V storage); ln2 compensates exactly.
    float inv0 = LN2 / rs0;
    float inv1 = LN2 / rs1;

    if (r0 < SS) {
        float* o = d_acc + ((size_t)b*SS + r0)*CC + h*HD + 2*t4;
        #pragma unroll
        for (int i = 0; i < 4; i++)
            *(float2*)(o + i*8) = make_float2(oacc[i][0]*inv0, oacc[i][1]*inv0);
    }
    if (r1i < SS) {
        float* o = d_acc + ((size_t)b*SS + r1i)*CC + h*HD + 2*t4;
        #pragma unroll
        for (int i = 0; i < 4; i++)
            *(float2*)(o + i*8) = make_float2(oacc[i][2]*inv1, oacc[i][3]*inv1);
    }
}

// ---------------------------------------------------------------------------
// Kernel 3: LEPE depthwise 5x5 conv + acc split to fp16 hi/lo.
// Interior positions (52x52) take a fully-unrolled branch-free path.
// ---------------------------------------------------------------------------
__global__ __launch_bounds__(256) void lepe_kernel(
    const float* __restrict__ lw, const float* __restrict__ lb)
{
    int blk = blockIdx.x;
    int b = blk / SS, srow = blk % SS;
    int c = threadIdx.x;
    size_t idx = ((size_t)b*SS + srow)*CC + c;
    float a = d_acc[idx];
    if (srow >= QN) {
        int p = srow - QN;
        int y = p / 56, x = p % 56;
        float l = lb[c];
        if (y >= 2 && y < 54 && x >= 2 && x < 54) {
            const float* vp = d_v + ((size_t)b*SS + QN + (y-2)*56 + (x-2))*CC + c;
            const float* wp = lw + c;
            #pragma unroll
            for (int ky = 0; ky < 5; ky++)
                #pragma unroll
                for (int kx = 0; kx < 5; kx++)
                    l += vp[(size_t)(ky*56 + kx)*CC] * wp[(size_t)(ky*5 + kx)*CC];
        } else {
            #pragma unroll
            for (int ky = 0; ky < 5; ky++) {
                int iy = y + ky - 2;
                if (iy < 0 || iy >= 56) continue;
                #pragma unroll
                for (int kx = 0; kx < 5; kx++) {
                    int ix = x + kx - 2;
                    if (ix < 0 || ix >= 56) continue;
                    l += d_v[((size_t)b*SS + QN + iy*56 + ix)*CC + c] * lw[(ky*5 + kx)*CC + c];
                }
            }
        }
        a += l;
    }
    __half h, lo; split_h(a, h, lo);
    d_acch[idx] = h;
    d_accl[idx] = lo;
}

// ---------------------------------------------------------------------------
// Kernel 4: output projection, split-fp16 HMMA (3-pass). 64x64 tiles.
// ---------------------------------------------------------------------------
__global__ __launch_bounds__(256) void out_kernel(
    const float* __restrict__ bo, float* __restrict__ out)
{
    __shared__ __align__(16) u16 Xh[64*40];
    __shared__ __align__(16) u16 Xl[64*40];
    __shared__ __align__(16) u16 Wh[64*40];
    __shared__ __align__(16) u16 Wl[64*40];

    const int m0 = blockIdx.x * 64;
    const int n0 = blockIdx.y * 64;
    const int t = threadIdx.x;
    const int w = t >> 5, lane = t & 31;
    const int g = lane >> 2, t4 = lane & 3;
    const int wr = w >> 1, wc = w & 1;

    float acc[4][4];
    #pragma unroll
    for (int i = 0; i < 4; i++)
        #pragma unroll
        for (int c = 0; c < 4; c++) acc[i][c] = 0.f;

    const u32 xb  = smem_u32(Xh), xlb = smem_u32(Xl);
    const u32 wb  = smem_u32(Wh), wlb = smem_u32(Wl);

    for (int kk = 0; kk < CC; kk += 32) {
        __syncthreads();
        {
            int r = t >> 2, c8 = (t & 3) * 8;
            int gm = m0 + r;
            uint4 a = make_uint4(0u,0u,0u,0u), bvv = make_uint4(0u,0u,0u,0u);
            if (gm < MTOT) {
                a   = *(const uint4*)&d_acch[(size_t)gm*CC + kk + c8];
                bvv = *(const uint4*)&d_accl[(size_t)gm*CC + kk + c8];
            }
            *(uint4*)&Xh[r*40 + c8] = a;
            *(uint4*)&Xl[r*40 + c8] = bvv;
            int wrow = n0 + r;
            *(uint4*)&Wh[r*40 + c8] = *(const uint4*)&d_woh[(size_t)wrow*CC + kk + c8];
            *(uint4*)&Wl[r*40 + c8] = *(const uint4*)&d_wol[(size_t)wrow*CC + kk + c8];
        }
        __syncthreads();

        u32 ax[2][4], al[2][4];
        #pragma unroll
        for (int ks = 0; ks < 2; ks++) {
            u32 aoff = (u32)(((16*wr + (lane & 15))*40 + ks*16 + ((lane>>4)&1)*8) * 2);
            ldx4(ax[ks], xb  + aoff);
            ldx4(al[ks], xlb + aoff);
        }
        #pragma unroll
        for (int ks = 0; ks < 2; ks++) {
            #pragma unroll
            for (int np = 0; np < 2; np++) {
                u32 boff = (u32)(((32*wc + np*16 + ((lane>>4)&1)*8 + (lane & 7))*40
                                  + ks*16 + ((lane>>3)&1)*8) * 2);
                u32 bh4[4], bl4[4];
                ldx4(bh4, wb  + boff);
                ldx4(bl4, wlb + boff);
                mma_h(acc[2*np],   ax[ks], bh4[0], bh4[1]);
                mma_h(acc[2*np],   ax[ks], bl4[0], bl4[1]);
                mma_h(acc[2*np],   al[ks], bh4[0], bh4[1]);
                mma_h(acc[2*np+1], ax[ks], bh4[2], bh4[3]);
                mma_h(acc[2*np+1], ax[ks], bl4[2], bl4[3]);
                mma_h(acc[2*np+1], al[ks], bh4[2], bh4[3]);
            }
        }
    }

    #pragma unroll
    for (int nt = 0; nt < 4; nt++) {
        int n = n0 + 32*wc + 8*nt + 2*t4;
        float b0v = bo[n], b1v = bo[n+1];
        #pragma unroll
        for (int rr = 0; rr < 2; rr++) {
            int gm = m0 + 16*wr + g + rr*8;
            if (gm >= MTOT) continue;
            *(float2*)&out[(size_t)gm*CC + n] =
                make_float2(acc[nt][2*rr] + b0v, acc[nt][2*rr+1] + b1v);
        }
    }
}

// ---------------------------------------------------------------------------
extern "C" void kernel_launch(void* const* d_in, const int* in_sizes, int n_in,
                              void* d_out, int out_size) {
    const float* x    = (const float*)d_in[0];
    const float* mask = (const float*)d_in[1];
    const float* wq   = (const float*)d_in[2];
    const float* bq   = (const float*)d_in[3];
    const float* wk   = (const float*)d_in[4];
    const float* bk   = (const float*)d_in[5];
    const float* wv   = (const float*)d_in[6];
    const float* bv   = (const float*)d_in[7];
    const float* lw   = (const float*)d_in[8];
    const float* lb   = (const float*)d_in[9];
    const float* wo   = (const float*)d_in[10];
    const float* bo   = (const float*)d_in[11];
    float* out = (float*)d_out;

    cvt_kernel<<<1024, 256>>>(wq, wk, wv, wo);
    mask16_kernel<<<(int)((NM/8 + 255)/256), 256>>>(mask);
    dim3 g1(99, 12);
    qkv_kernel<<<g1, 256>>>(x, bq, bk, bv);
    dim3 g2(BB*4, NQT64);
    attn_mma_kernel<<<g2, 256>>>();
    lepe_kernel<<<BB*SS, 256>>>(lw, lb);
    dim3 g4(99, 4);
    out_kernel<<<g4, 256>>>(bo, out);
}

// round 12
// speedup vs baseline: 1.1961x; 1.1961x over previous
#include <cuda_runtime.h>
#include <cuda_fp16.h>
#include <cstdint>

#define BB 2
#define SS 3144
#define CC 256
#define HH 8
#define HD 32
#define QN 8
#define MTOT (BB*SS)            /* 6288 */
#define SCALE 0.1767766952966369f
#define KSCALE (0.1767766952966369f * 1.44269504f)   /* SCALE * log2(e) */
#define LN2 0.6931471805599453f
#define NKT2 ((SS + 63) / 64)   /* 50 key tiles of 64 */
#define NQT64 ((SS + 63) / 64)  /* 50 query tiles of 64 */
#define NM ((size_t)BB*SS*SS)

typedef unsigned long long u64;
typedef unsigned int u32;
typedef unsigned short u16;

__device__ __align__(16) __half d_qh[BB*HH*SS*HD];  // head-major fp16
__device__ __align__(16) __half d_kh[BB*HH*SS*HD];  // scaled by KSCALE (K and V)
__device__ __align__(16) float  d_v[BB*SS*CC];
__device__ __align__(16) float  d_acc[BB*SS*CC];    // attention out (f32)
__device__ __align__(16) __half d_m16[BB*SS*SS];    // (mask + 1e-6) in fp16
__device__ __align__(16) __half d_wh[768*CC];       // [wq;wk;wv] split
__device__ __align__(16) __half d_wl[768*CC];
__device__ __align__(16) __half d_woh[CC*CC];       // wo split
__device__ __align__(16) __half d_wol[CC*CC];
__device__ __align__(16) __half d_acch[BB*SS*CC];   // acc(+lepe) split
__device__ __align__(16) __half d_accl[BB*SS*CC];

// ---------------- helpers ----------------
__device__ __forceinline__ u32 smem_u32(const void* p) {
    u32 a;
    asm("{ .reg .u64 t; cvta.to.shared.u64 t, %1; cvt.u32.u64 %0, t; }" : "=r"(a) : "l"(p));
    return a;
}
__device__ __forceinline__ u32 pack_h2(float lo, float hi) {
    u32 r; asm("cvt.rn.f16x2.f32 %0, %1, %2;" : "=r"(r) : "f"(hi), "f"(lo)); return r;
}
__device__ __forceinline__ u32 ex2h2(u32 x) {
    u32 r; asm("ex2.approx.f16x2 %0, %1;" : "=r"(r) : "r"(x)); return r;
}
__device__ __forceinline__ u32 hmul2u(u32 a, u32 b) {
    u32 r; asm("mul.rn.f16x2 %0, %1, %2;" : "=r"(r) : "r"(a), "r"(b)); return r;
}
__device__ __forceinline__ u32 hadd2u(u32 a, u32 b) {
    u32 r; asm("add.rn.f16x2 %0, %1, %2;" : "=r"(r) : "r"(a), "r"(b)); return r;
}
__device__ __forceinline__ void ldx4(u32* r, u32 saddr) {
    asm volatile("ldmatrix.sync.aligned.m8n8.x4.shared.b16 {%0,%1,%2,%3}, [%4];"
                 : "=r"(r[0]), "=r"(r[1]), "=r"(r[2]), "=r"(r[3]) : "r"(saddr));
}
__device__ __forceinline__ void ldx4t(u32* r, u32 saddr) {
    asm volatile("ldmatrix.sync.aligned.m8n8.x4.trans.shared.b16 {%0,%1,%2,%3}, [%4];"
                 : "=r"(r[0]), "=r"(r[1]), "=r"(r[2]), "=r"(r[3]) : "r"(saddr));
}
__device__ __forceinline__ void mma_h(float* c, const u32* a, u32 b0, u32 b1) {
    asm volatile("mma.sync.aligned.m16n8k16.row.col.f32.f16.f16.f32 "
                 "{%0,%1,%2,%3}, {%4,%5,%6,%7}, {%8,%9}, {%0,%1,%2,%3};"
                 : "+f"(c[0]), "+f"(c[1]), "+f"(c[2]), "+f"(c[3])
                 : "r"(a[0]), "r"(a[1]), "r"(a[2]), "r"(a[3]), "r"(b0), "r"(b1));
}
__device__ __forceinline__ void split_h(float v, __half &h, __half &l) {
    h = __float2half_rn(v);
    l = __float2half_rn(v - __half2float(h));
}

// ---------------------------------------------------------------------------
// Kernel 0a: split [wq;wk;wv], wo into fp16 hi/lo (weights only)
// ---------------------------------------------------------------------------
__global__ __launch_bounds__(256) void cvt_kernel(
    const float* __restrict__ wq, const float* __restrict__ wk,
    const float* __restrict__ wv, const float* __restrict__ wo)
{
    int j = blockIdx.x * 256 + threadIdx.x;      // 0 .. 4*65536-1
    int sec = j >> 16, off = j & 65535;
    const float* src = (sec == 0) ? wq : (sec == 1) ? wk : (sec == 2) ? wv : wo;
    __half h, l; split_h(src[off], h, l);
    if (sec < 3) { d_wh[j] = h; d_wl[j] = l; }
    else         { d_woh[off] = h; d_wol[off] = l; }
}

// ---------------------------------------------------------------------------
// Kernel 0b: mask -> fp16 with +1e-6 folded in
// ---------------------------------------------------------------------------
__global__ __launch_bounds__(256) void mask16_kernel(const float* __restrict__ m)
{
    size_t i = ((size_t)blockIdx.x * 256 + threadIdx.x) * 8;
    if (i >= NM) return;
    float4 a = *(const float4*)(m + i);
    float4 b = *(const float4*)(m + i + 4);
    __half hh[8];
    hh[0] = __float2half_rn(a.x + 1e-6f);
    hh[1] = __float2half_rn(a.y + 1e-6f);
    hh[2] = __float2half_rn(a.z + 1e-6f);
    hh[3] = __float2half_rn(a.w + 1e-6f);
    hh[4] = __float2half_rn(b.x + 1e-6f);
    hh[5] = __float2half_rn(b.y + 1e-6f);
    hh[6] = __float2half_rn(b.z + 1e-6f);
    hh[7] = __float2half_rn(b.w + 1e-6f);
    *(uint4*)&d_m16[i] = *(uint4*)hh;
}

// ---------------------------------------------------------------------------
// Kernel 1: fused QKV projection. x split in-kernel.
// q,k sections: single-pass fp16 HMMA. v section: 3-pass split-fp16.
// ---------------------------------------------------------------------------
__global__ __launch_bounds__(256) void qkv_kernel(
    const float* __restrict__ x,
    const float* __restrict__ bq, const float* __restrict__ bk,
    const float* __restrict__ bv)
{
    __shared__ __align__(16) u16 Xh[64*40];
    __shared__ __align__(16) u16 Xl[64*40];
    __shared__ __align__(16) u16 Wh[64*40];
    __shared__ __align__(16) u16 Wl[64*40];

    const int m0 = blockIdx.x * 64;
    const int n0 = blockIdx.y * 64;       // global 0..767
    const int t = threadIdx.x;
    const int w = t >> 5, lane = t & 31;
    const int g = lane >> 2, t4 = lane & 3;
    const int wr = w >> 1, wc = w & 1;
    const int sec = n0 >> 8;
    const int nbase = n0 & 255;
    const bool isv = (sec == 2);

    float acc[4][4];
    #pragma unroll
    for (int i = 0; i < 4; i++)
        #pragma unroll
        for (int c = 0; c < 4; c++) acc[i][c] = 0.f;

    const u32 xb  = smem_u32(Xh), xlb = smem_u32(Xl);
    const u32 wb  = smem_u32(Wh), wlb = smem_u32(Wl);

    for (int kk = 0; kk < CC; kk += 32) {
        __syncthreads();
        {
            int r = t >> 2, c8 = (t & 3) * 8;
            int gm = m0 + r;
            float4 f0 = make_float4(0.f,0.f,0.f,0.f), f1 = f0;
            if (gm < MTOT) {
                f0 = *(const float4*)(x + (size_t)gm*CC + kk + c8);
                f1 = *(const float4*)(x + (size_t)gm*CC + kk + c8 + 4);
            }
            float vv[8] = {f0.x,f0.y,f0.z,f0.w,f1.x,f1.y,f1.z,f1.w};
            __half hh[8], ll[8];
            #pragma unroll
            for (int i = 0; i < 8; i++) split_h(vv[i], hh[i], ll[i]);
            *(uint4*)&Xh[r*40 + c8] = *(uint4*)hh;
            if (isv) *(uint4*)&Xl[r*40 + c8] = *(uint4*)ll;
            int wrow = n0 + r;
            *(uint4*)&Wh[r*40 + c8] = *(const uint4*)&d_wh[(size_t)wrow*CC + kk + c8];
            if (isv) *(uint4*)&Wl[r*40 + c8] = *(const uint4*)&d_wl[(size_t)wrow*CC + kk + c8];
        }
        __syncthreads();

        u32 ax[2][4], al[2][4];
        #pragma unroll
        for (int ks = 0; ks < 2; ks++) {
            u32 aoff = (u32)(((16*wr + (lane & 15))*40 + ks*16 + ((lane>>4)&1)*8) * 2);
            ldx4(ax[ks], xb + aoff);
            if (isv) ldx4(al[ks], xlb + aoff);
        }
        #pragma unroll
        for (int ks = 0; ks < 2; ks++) {
            #pragma unroll
            for (int np = 0; np < 2; np++) {
                u32 boff = (u32)(((32*wc + np*16 + ((lane>>4)&1)*8 + (lane & 7))*40
                                  + ks*16 + ((lane>>3)&1)*8) * 2);
                u32 bh4[4];
                ldx4(bh4, wb + boff);
                mma_h(acc[2*np],   ax[ks], bh4[0], bh4[1]);
                mma_h(acc[2*np+1], ax[ks], bh4[2], bh4[3]);
                if (isv) {
                    u32 bl4[4];
                    ldx4(bl4, wlb + boff);
                    mma_h(acc[2*np],   ax[ks], bl4[0], bl4[1]);
                    mma_h(acc[2*np],   al[ks], bh4[0], bh4[1]);
                    mma_h(acc[2*np+1], ax[ks], bl4[2], bl4[3]);
                    mma_h(acc[2*np+1], al[ks], bh4[2], bh4[3]);
                }
            }
        }
    }

    const float* bsec = (sec == 0) ? bq : (sec == 1) ? bk : bv;
    #pragma unroll
    for (int nt = 0; nt < 4; nt++) {
        int ct = 32*wc + 8*nt + 2*t4;
        int c = nbase + ct;
        float b0v = bsec[c], b1v = bsec[c+1];
        #pragma unroll
        for (int rr = 0; rr < 2; rr++) {
            int gm = m0 + 16*wr + g + rr*8;
            if (gm >= MTOT) continue;
            float v0 = acc[nt][2*rr]   + b0v;
            float v1 = acc[nt][2*rr+1] + b1v;
            int b = gm / SS, srow = gm % SS;
            if (sec == 0) {
                *(__half2*)&d_qh[(((size_t)b*HH + (c>>5))*SS + srow)*HD + (c&31)] =
                    __floats2half2_rn(v0, v1);
            } else if (sec == 1) {
                *(__half2*)&d_kh[(((size_t)b*HH + (c>>5))*SS + srow)*HD + (c&31)] =
                    __floats2half2_rn(v0*KSCALE, v1*KSCALE);
            } else {
                *(float2*)&d_v[(size_t)gm*CC + c] = make_float2(v0, v1);
            }
        }
    }
}

// ---------------------------------------------------------------------------
// Kernel 2: fp16 mma.sync attention — 2 heads per block, fp32 accumulators.
// K pre-scaled by SCALE*log2e; epilogue in packed fp16:
//   wh = mul.f16x2(m16, ex2.approx.f16x2(pack(s0,s1)))
// Rowsum in f16x2 with per-k-tile f32 flush. Final *= ln2 / rowsum.
// ---------------------------------------------------------------------------
__global__ void __launch_bounds__(256, 3) attn_mma_kernel()
{
    __shared__ __align__(16) u16 Qsm[2*64*40];     // 10240 B (2 heads)
    __shared__ __align__(16) u16 Ksm[2*2*64*40];   // 20480 B (2 heads x double buf)

    const int t = threadIdx.x;
    const int w = t >> 5, lane = t & 31;
    const int g = lane >> 2, t4 = lane & 3;
    const int hp = w >> 2, w4 = w & 3;
    const int bhp = blockIdx.x;
    const int b = bhp >> 2, hpair = bhp & 3;
    const int h = hpair*2 + hp;
    const int q0 = blockIdx.y * 64;

    // ---- stage Q tiles for both heads ----
    {
        int hld = t >> 7, r = (t >> 1) & 63, part = t & 1;
        const __half* qb2 = d_qh + (((size_t)b*HH + hpair*2 + hld) * SS) * HD;
        int gq = q0 + r;
        uint4 a0 = make_uint4(0u,0u,0u,0u), a1 = make_uint4(0u,0u,0u,0u);
        if (gq < SS) {
            a0 = *(const uint4*)(qb2 + (size_t)gq*HD + part*16);
            a1 = *(const uint4*)(qb2 + (size_t)gq*HD + part*16 + 8);
        }
        *(uint4*)&Qsm[hld*64*40 + r*40 + part*16]     = a0;
        *(uint4*)&Qsm[hld*64*40 + r*40 + part*16 + 8] = a1;
    }
    __syncthreads();

    u32 qa[2][4];
    {
        u32 qs = smem_u32(Qsm) + (u32)(hp*64*40*2);
        int row = 16*w4 + (lane & 15);
        int cb = (lane >> 4) * 8;
        ldx4(qa[0], qs + (u32)((row*40 + cb) * 2));
        ldx4(qa[1], qs + (u32)((row*40 + cb + 16) * 2));
    }

    const u32 ks_base = smem_u32(Ksm);

    const int r0  = q0 + 16*w4 + g;
    const int r1i = r0 + 8;
    const __half* mbb = d_m16 + (size_t)b * SS * SS;
    const __half* mr0 = (r0  < SS) ? mbb + (size_t)r0  * SS : (const __half*)0;
    const __half* mr1 = (r1i < SS) ? mbb + (size_t)r1i * SS : (const __half*)0;

    float oacc[4][4];
    #pragma unroll
    for (int i = 0; i < 4; i++)
        #pragma unroll
        for (int c = 0; c < 4; c++) oacc[i][c] = 0.f;
    float rs0 = 0.f, rs1 = 0.f;

    // mask prefetch double-buffer (f16x2 pairs)
    u32 mbuf[2][4];
    auto do_pref = [&](int gjdx, u32* dst) {
        int base = gjdx * 16;
        #pragma unroll
        for (int p = 0; p < 2; p++) {
            int gk = base + p*8 + 2*t4;
            u32 v0 = 0u, v1 = 0u;
            if (gk < SS) {
                if (mr0) v0 = *(const u32*)(mr0 + gk);
                if (mr1) v1 = *(const u32*)(mr1 + gk);
            }
            dst[2*p]   = v0;
            dst[2*p+1] = v1;
        }
    };
    do_pref(0, mbuf[0]);

    // K tile load/store: 256 thr cover 2 heads x 64 rows x 32 halves
    const int khld = t >> 7, kkr = (t >> 1) & 63, kpart = t & 1;
    const __half* kldb = d_kh + (((size_t)b*HH + hpair*2 + khld) * SS) * HD;
    auto ldK = [&](int kt, uint4 &a0, uint4 &a1) {
        int gk = kt*64 + kkr;
        a0 = make_uint4(0u,0u,0u,0u); a1 = make_uint4(0u,0u,0u,0u);
        if (gk < SS) {
            a0 = *(const uint4*)(kldb + (size_t)gk*HD + kpart*16);
            a1 = *(const uint4*)(kldb + (size_t)gk*HD + kpart*16 + 8);
        }
    };
    auto stK = [&](int buf, uint4 a0, uint4 a1) {
        int base = (khld*2 + buf)*64*40;
        *(uint4*)&Ksm[base + kkr*40 + kpart*16]     = a0;
        *(uint4*)&Ksm[base + kkr*40 + kpart*16 + 8] = a1;
    };

    {
        uint4 p0, p1;
        ldK(0, p0, p1);
        stK(0, p0, p1);
    }
    __syncthreads();

    for (int kt = 0; kt < NKT2; kt++) {
        const u32 ks = ks_base + (u32)(((hp*2 + (kt & 1)) * 64*40) * 2);
        const bool more = (kt + 1 < NKT2);
        uint4 n0v, n1v;
        if (more) ldK(kt + 1, n0v, n1v);

        u32 rsh0 = 0u, rsh1 = 0u;         // per-tile f16x2 rowsum

        #pragma unroll
        for (int j = 0; j < 4; j++) {
            const u32* mc = mbuf[j & 1];
            // ---- QK (fp32 acc) ----
            float sc[2][4];
            #pragma unroll
            for (int p = 0; p < 2; p++) {
                #pragma unroll
                for (int c = 0; c < 4; c++) sc[p][c] = 0.f;
                int nt = 2*j + p;
                u32 br[4];
                ldx4(br, ks + (u32)(((nt*8 + (lane & 7))*40 + ((lane>>3)&3)*8) * 2));
                mma_h(sc[p], qa[0], br[0], br[1]);
                mma_h(sc[p], qa[1], br[2], br[3]);
            }
            // prefetch next chunk's mask
            {
                int gn = kt*4 + j + 1;
                if (gn < NKT2*4) do_pref(gn, mbuf[(j+1) & 1]);
            }
            // ---- epilogue (packed fp16): w = m16 * 2^s ----
            u32 wh[4];
            #pragma unroll
            for (int p = 0; p < 2; p++) {
                u32 s01 = pack_h2(sc[p][0], sc[p][1]);
                u32 s23 = pack_h2(sc[p][2], sc[p][3]);
                u32 w0 = hmul2u(mc[2*p],   ex2h2(s01));
                u32 w1 = hmul2u(mc[2*p+1], ex2h2(s23));
                rsh0 = hadd2u(rsh0, w0);
                rsh1 = hadd2u(rsh1, w1);
                wh[2*p]   = w0;
                wh[2*p+1] = w1;
            }
            // ---- PV via trans-ldmatrix straight from K tile ----
            #pragma unroll
            for (int ip = 0; ip < 2; ip++) {
                u32 vr[4];
                ldx4t(vr, ks + (u32)(((16*j + ((lane>>3)&1)*8 + (lane & 7))*40
                                      + ((lane>>4)&1)*8 + ip*16) * 2));
                mma_h(oacc[2*ip],   wh, vr[0], vr[1]);
                mma_h(oacc[2*ip+1], wh, vr[2], vr[3]);
            }
        }

        // flush per-tile rowsum to f32
        {
            float2 f0 = __half22float2(*reinterpret_cast<__half2*>(&rsh0));
            float2 f1 = __half22float2(*reinterpret_cast<__half2*>(&rsh1));
            rs0 += f0.x + f0.y;
            rs1 += f1.x + f1.y;
        }

        if (more) stK((kt + 1) & 1, n0v, n1v);
        __syncthreads();
    }

    rs0 += __shfl_xor_sync(0xffffffffu, rs0, 1);
    rs0 += __shfl_xor_sync(0xffffffffu, rs0, 2);
    rs1 += __shfl_xor_sync(0xffffffffu, rs1, 1);
    rs1 += __shfl_xor_sync(0xffffffffu, rs1, 2);
    // V carried an extra log2(e) factor (K==V storage); ln2 compensates exactly.
    float inv0 = LN2 / rs0;
    float inv1 = LN2 / rs1;

    if (r0 < SS) {
        float* o = d_acc + ((size_t)b*SS + r0)*CC + h*HD + 2*t4;
        #pragma unroll
        for (int i = 0; i < 4; i++)
            *(float2*)(o + i*8) = make_float2(oacc[i][0]*inv0, oacc[i][1]*inv0);
    }
    if (r1i < SS) {
        float* o = d_acc + ((size_t)b*SS + r1i)*CC + h*HD + 2*t4;
        #pragma unroll
        for (int i = 0; i < 4; i++)
            *(float2*)(o + i*8) = make_float2(oacc[i][2]*inv1, oacc[i][3]*inv1);
    }
}

// ---------------------------------------------------------------------------
// Kernel 3: LEPE depthwise 5x5 conv + acc split to fp16 hi/lo.
// Interior positions (52x52) take a fully-unrolled branch-free path.
// ---------------------------------------------------------------------------
__global__ __launch_bounds__(256) void lepe_kernel(
    const float* __restrict__ lw, const float* __restrict__ lb)
{
    int blk = blockIdx.x;
    int b = blk / SS, srow = blk % SS;
    int c = threadIdx.x;
    size_t idx = ((size_t)b*SS + srow)*CC + c;
    float a = d_acc[idx];
    if (srow >= QN) {
        int p = srow - QN;
        int y = p / 56, x = p % 56;
        float l = lb[c];
        if (y >= 2 && y < 54 && x >= 2 && x < 54) {
            const float* vp = d_v + ((size_t)b*SS + QN + (y-2)*56 + (x-2))*CC + c;
            const float* wp = lw + c;
            #pragma unroll
            for (int ky = 0; ky < 5; ky++)
                #pragma unroll
                for (int kx = 0; kx < 5; kx++)
                    l += vp[(size_t)(ky*56 + kx)*CC] * wp[(size_t)(ky*5 + kx)*CC];
        } else {
            #pragma unroll
            for (int ky = 0; ky < 5; ky++) {
                int iy = y + ky - 2;
                if (iy < 0 || iy >= 56) continue;
                #pragma unroll
                for (int kx = 0; kx < 5; kx++) {
                    int ix = x + kx - 2;
                    if (ix < 0 || ix >= 56) continue;
                    l += d_v[((size_t)b*SS + QN + iy*56 + ix)*CC + c] * lw[(ky*5 + kx)*CC + c];
                }
            }
        }
        a += l;
    }
    __half h, lo; split_h(a, h, lo);
    d_acch[idx] = h;
    d_accl[idx] = lo;
}

// ---------------------------------------------------------------------------
// Kernel 4: output projection, split-fp16 HMMA (3-pass). 64x64 tiles.
// ---------------------------------------------------------------------------
__global__ __launch_bounds__(256) void out_kernel(
    const float* __restrict__ bo, float* __restrict__ out)
{
    __shared__ __align__(16) u16 Xh[64*40];
    __shared__ __align__(16) u16 Xl[64*40];
    __shared__ __align__(16) u16 Wh[64*40];
    __shared__ __align__(16) u16 Wl[64*40];

    const int m0 = blockIdx.x * 64;
    const int n0 = blockIdx.y * 64;
    const int t = threadIdx.x;
    const int w = t >> 5, lane = t & 31;
    const int g = lane >> 2, t4 = lane & 3;
    const int wr = w >> 1, wc = w & 1;

    float acc[4][4];
    #pragma unroll
    for (int i = 0; i < 4; i++)
        #pragma unroll
        for (int c = 0; c < 4; c++) acc[i][c] = 0.f;

    const u32 xb  = smem_u32(Xh), xlb = smem_u32(Xl);
    const u32 wb  = smem_u32(Wh), wlb = smem_u32(Wl);

    for (int kk = 0; kk < CC; kk += 32) {
        __syncthreads();
        {
            int r = t >> 2, c8 = (t & 3) * 8;
            int gm = m0 + r;
            uint4 a = make_uint4(0u,0u,0u,0u), bvv = make_uint4(0u,0u,0u,0u);
            if (gm < MTOT) {
                a   = *(const uint4*)&d_acch[(size_t)gm*CC + kk + c8];
                bvv = *(const uint4*)&d_accl[(size_t)gm*CC + kk + c8];
            }
            *(uint4*)&Xh[r*40 + c8] = a;
            *(uint4*)&Xl[r*40 + c8] = bvv;
            int wrow = n0 + r;
            *(uint4*)&Wh[r*40 + c8] = *(const uint4*)&d_woh[(size_t)wrow*CC + kk + c8];
            *(uint4*)&Wl[r*40 + c8] = *(const uint4*)&d_wol[(size_t)wrow*CC + kk + c8];
        }
        __syncthreads();

        u32 ax[2][4], al[2][4];
        #pragma unroll
        for (int ks = 0; ks < 2; ks++) {
            u32 aoff = (u32)(((16*wr + (lane & 15))*40 + ks*16 + ((lane>>4)&1)*8) * 2);
            ldx4(ax[ks], xb  + aoff);
            ldx4(al[ks], xlb + aoff);
        }
        #pragma unroll
        for (int ks = 0; ks < 2; ks++) {
            #pragma unroll
            for (int np = 0; np < 2; np++) {
                u32 boff = (u32)(((32*wc + np*16 + ((lane>>4)&1)*8 + (lane & 7))*40
                                  + ks*16 + ((lane>>3)&1)*8) * 2);
                u32 bh4[4], bl4[4];
                ldx4(bh4, wb  + boff);
                ldx4(bl4, wlb + boff);
                mma_h(acc[2*np],   ax[ks], bh4[0], bh4[1]);
                mma_h(acc[2*np],   ax[ks], bl4[0], bl4[1]);
                mma_h(acc[2*np],   al[ks], bh4[0], bh4[1]);
                mma_h(acc[2*np+1], ax[ks], bh4[2], bh4[3]);
                mma_h(acc[2*np+1], ax[ks], bl4[2], bl4[3]);
                mma_h(acc[2*np+1], al[ks], bh4[2], bh4[3]);
            }
        }
    }

    #pragma unroll
    for (int nt = 0; nt < 4; nt++) {
        int n = n0 + 32*wc + 8*nt + 2*t4;
        float b0v = bo[n], b1v = bo[n+1];
        #pragma unroll
        for (int rr = 0; rr < 2; rr++) {
            int gm = m0 + 16*wr + g + rr*8;
            if (gm >= MTOT) continue;
            *(float2*)&out[(size_t)gm*CC + n] =
                make_float2(acc[nt][2*rr] + b0v, acc[nt][2*rr+1] + b1v);
        }
    }
}

// ---------------------------------------------------------------------------
extern "C" void kernel_launch(void* const* d_in, const int* in_sizes, int n_in,
                              void* d_out, int out_size) {
    const float* x    = (const float*)d_in[0];
    const float* mask = (const float*)d_in[1];
    const float* wq   = (const float*)d_in[2];
    const float* bq   = (const float*)d_in[3];
    const float* wk   = (const float*)d_in[4];
    const float* bk   = (const float*)d_in[5];
    const float* wv   = (const float*)d_in[6];
    const float* bv   = (const float*)d_in[7];
    const float* lw   = (const float*)d_in[8];
    const float* lb   = (const float*)d_in[9];
    const float* wo   = (const float*)d_in[10];
    const float* bo   = (const float*)d_in[11];
    float* out = (float*)d_out;

    cvt_kernel<<<1024, 256>>>(wq, wk, wv, wo);
    mask16_kernel<<<(int)((NM/8 + 255)/256), 256>>>(mask);
    dim3 g1(99, 12);
    qkv_kernel<<<g1, 256>>>(x, bq, bk, bv);
    dim3 g2(BB*4, NQT64);
    attn_mma_kernel<<<g2, 256>>>();
    lepe_kernel<<<BB*SS, 256>>>(lw, lb);
    dim3 g4(99, 4);
    out_kernel<<<g4, 256>>>(bo, out);
}

// round 13
// speedup vs baseline: 1.2401x; 1.0368x over previous
#include <cuda_runtime.h>
#include <cuda_fp16.h>
#include <cstdint>

#define BB 2
#define SS 3144
#define CC 256
#define HH 8
#define HD 32
#define QN 8
#define MTOT (BB*SS)            /* 6288 */
#define SCALE 0.1767766952966369f
#define KSCALE (0.1767766952966369f * 1.44269504f)   /* SCALE * log2(e) */
#define LN2 0.6931471805599453f
#define NKT2 ((SS + 63) / 64)   /* 50 key tiles of 64 */
#define NQT64 ((SS + 63) / 64)  /* 50 query tiles of 64 */
#define NM ((size_t)BB*SS*SS)

typedef unsigned long long u64;
typedef unsigned int u32;
typedef unsigned short u16;

__device__ __align__(16) __half d_qh[BB*HH*SS*HD];  // head-major fp16
__device__ __align__(16) __half d_kh[BB*HH*SS*HD];  // scaled by KSCALE (K and V)
__device__ __align__(16) float  d_v[BB*SS*CC];
__device__ __align__(16) float  d_acc[BB*SS*CC];    // attention out (f32)
__device__ __align__(16) __half d_m16[BB*SS*SS];    // (mask + 1e-6) in fp16
__device__ __align__(16) __half d_wh[768*CC];       // [wq;wk;wv] split
__device__ __align__(16) __half d_wl[768*CC];
__device__ __align__(16) __half d_woh[CC*CC];       // wo split
__device__ __align__(16) __half d_wol[CC*CC];
__device__ __align__(16) __half d_acch[BB*SS*CC];   // acc(+lepe) split
__device__ __align__(16) __half d_accl[BB*SS*CC];

// ---------------- helpers ----------------
__device__ __forceinline__ u32 smem_u32(const void* p) {
    u32 a;
    asm("{ .reg .u64 t; cvta.to.shared.u64 t, %1; cvt.u32.u64 %0, t; }" : "=r"(a) : "l"(p));
    return a;
}
__device__ __forceinline__ u32 pack_h2(float lo, float hi) {
    u32 r; asm("cvt.rn.f16x2.f32 %0, %1, %2;" : "=r"(r) : "f"(hi), "f"(lo)); return r;
}
__device__ __forceinline__ u32 ex2h2(u32 x) {
    u32 r; asm("ex2.approx.f16x2 %0, %1;" : "=r"(r) : "r"(x)); return r;
}
__device__ __forceinline__ u32 hmul2u(u32 a, u32 b) {
    u32 r; asm("mul.rn.f16x2 %0, %1, %2;" : "=r"(r) : "r"(a), "r"(b)); return r;
}
__device__ __forceinline__ u32 hadd2u(u32 a, u32 b) {
    u32 r; asm("add.rn.f16x2 %0, %1, %2;" : "=r"(r) : "r"(a), "r"(b)); return r;
}
__device__ __forceinline__ void ldx4(u32* r, u32 saddr) {
    asm volatile("ldmatrix.sync.aligned.m8n8.x4.shared.b16 {%0,%1,%2,%3}, [%4];"
                 : "=r"(r[0]), "=r"(r[1]), "=r"(r[2]), "=r"(r[3]) : "r"(saddr));
}
__device__ __forceinline__ void ldx4t(u32* r, u32 saddr) {
    asm volatile("ldmatrix.sync.aligned.m8n8.x4.trans.shared.b16 {%0,%1,%2,%3}, [%4];"
                 : "=r"(r[0]), "=r"(r[1]), "=r"(r[2]), "=r"(r[3]) : "r"(saddr));
}
__device__ __forceinline__ void mma_h(float* c, const u32* a, u32 b0, u32 b1) {
    asm volatile("mma.sync.aligned.m16n8k16.row.col.f32.f16.f16.f32 "
                 "{%0,%1,%2,%3}, {%4,%5,%6,%7}, {%8,%9}, {%0,%1,%2,%3};"
                 : "+f"(c[0]), "+f"(c[1]), "+f"(c[2]), "+f"(c[3])
                 : "r"(a[0]), "r"(a[1]), "r"(a[2]), "r"(a[3]), "r"(b0), "r"(b1));
}
__device__ __forceinline__ void split_h(float v, __half &h, __half &l) {
    h = __float2half_rn(v);
    l = __float2half_rn(v - __half2float(h));
}
__device__ __forceinline__ void cp16(u32 dst, const void* src, u32 sz) {
    asm volatile("cp.async.ca.shared.global [%0], [%1], 16, %2;"
                 :: "r"(dst), "l"(src), "r"(sz));
}
#define CP_COMMIT() asm volatile("cp.async.commit_group;" ::: "memory")
#define CP_WAIT0()  asm volatile("cp.async.wait_group 0;" ::: "memory")

// ---------------------------------------------------------------------------
// Kernel 0a: split [wq;wk;wv], wo into fp16 hi/lo (weights only)
// ---------------------------------------------------------------------------
__global__ __launch_bounds__(256) void cvt_kernel(
    const float* __restrict__ wq, const float* __restrict__ wk,
    const float* __restrict__ wv, const float* __restrict__ wo)
{
    int j = blockIdx.x * 256 + threadIdx.x;      // 0 .. 4*65536-1
    int sec = j >> 16, off = j & 65535;
    const float* src = (sec == 0) ? wq : (sec == 1) ? wk : (sec == 2) ? wv : wo;
    __half h, l; split_h(src[off], h, l);
    if (sec < 3) { d_wh[j] = h; d_wl[j] = l; }
    else         { d_woh[off] = h; d_wol[off] = l; }
}

// ---------------------------------------------------------------------------
// Kernel 0b: mask -> fp16 with +1e-6 folded in
// ---------------------------------------------------------------------------
__global__ __launch_bounds__(256) void mask16_kernel(const float* __restrict__ m)
{
    size_t i = ((size_t)blockIdx.x * 256 + threadIdx.x) * 8;
    if (i >= NM) return;
    float4 a = *(const float4*)(m + i);
    float4 b = *(const float4*)(m + i + 4);
    __half hh[8];
    hh[0] = __float2half_rn(a.x + 1e-6f);
    hh[1] = __float2half_rn(a.y + 1e-6f);
    hh[2] = __float2half_rn(a.z + 1e-6f);
    hh[3] = __float2half_rn(a.w + 1e-6f);
    hh[4] = __float2half_rn(b.x + 1e-6f);
    hh[5] = __float2half_rn(b.y + 1e-6f);
    hh[6] = __float2half_rn(b.z + 1e-6f);
    hh[7] = __float2half_rn(b.w + 1e-6f);
    *(uint4*)&d_m16[i] = *(uint4*)hh;
}

// ---------------------------------------------------------------------------
// Kernel 1: fused QKV projection. x split in-kernel.
// q,k sections: single-pass fp16 HMMA. v section: 3-pass split-fp16.
// ---------------------------------------------------------------------------
__global__ __launch_bounds__(256) void qkv_kernel(
    const float* __restrict__ x,
    const float* __restrict__ bq, const float* __restrict__ bk,
    const float* __restrict__ bv)
{
    __shared__ __align__(16) u16 Xh[64*40];
    __shared__ __align__(16) u16 Xl[64*40];
    __shared__ __align__(16) u16 Wh[64*40];
    __shared__ __align__(16) u16 Wl[64*40];

    const int m0 = blockIdx.x * 64;
    const int n0 = blockIdx.y * 64;       // global 0..767
    const int t = threadIdx.x;
    const int w = t >> 5, lane = t & 31;
    const int g = lane >> 2, t4 = lane & 3;
    const int wr = w >> 1, wc = w & 1;
    const int sec = n0 >> 8;
    const int nbase = n0 & 255;
    const bool isv = (sec == 2);

    float acc[4][4];
    #pragma unroll
    for (int i = 0; i < 4; i++)
        #pragma unroll
        for (int c = 0; c < 4; c++) acc[i][c] = 0.f;

    const u32 xb  = smem_u32(Xh), xlb = smem_u32(Xl);
    const u32 wb  = smem_u32(Wh), wlb = smem_u32(Wl);

    for (int kk = 0; kk < CC; kk += 32) {
        __syncthreads();
        {
            int r = t >> 2, c8 = (t & 3) * 8;
            int gm = m0 + r;
            float4 f0 = make_float4(0.f,0.f,0.f,0.f), f1 = f0;
            if (gm < MTOT) {
                f0 = *(const float4*)(x + (size_t)gm*CC + kk + c8);
                f1 = *(const float4*)(x + (size_t)gm*CC + kk + c8 + 4);
            }
            float vv[8] = {f0.x,f0.y,f0.z,f0.w,f1.x,f1.y,f1.z,f1.w};
            __half hh[8], ll[8];
            #pragma unroll
            for (int i = 0; i < 8; i++) split_h(vv[i], hh[i], ll[i]);
            *(uint4*)&Xh[r*40 + c8] = *(uint4*)hh;
            if (isv) *(uint4*)&Xl[r*40 + c8] = *(uint4*)ll;
            int wrow = n0 + r;
            *(uint4*)&Wh[r*40 + c8] = *(const uint4*)&d_wh[(size_t)wrow*CC + kk + c8];
            if (isv) *(uint4*)&Wl[r*40 + c8] = *(const uint4*)&d_wl[(size_t)wrow*CC + kk + c8];
        }
        __syncthreads();

        u32 ax[2][4], al[2][4];
        #pragma unroll
        for (int ks = 0; ks < 2; ks++) {
            u32 aoff = (u32)(((16*wr + (lane & 15))*40 + ks*16 + ((lane>>4)&1)*8) * 2);
            ldx4(ax[ks], xb + aoff);
            if (isv) ldx4(al[ks], xlb + aoff);
        }
        #pragma unroll
        for (int ks = 0; ks < 2; ks++) {
            #pragma unroll
            for (int np = 0; np < 2; np++) {
                u32 boff = (u32)(((32*wc + np*16 + ((lane>>4)&1)*8 + (lane & 7))*40
                                  + ks*16 + ((lane>>3)&1)*8) * 2);
                u32 bh4[4];
                ldx4(bh4, wb + boff);
                mma_h(acc[2*np],   ax[ks], bh4[0], bh4[1]);
                mma_h(acc[2*np+1], ax[ks], bh4[2], bh4[3]);
                if (isv) {
                    u32 bl4[4];
                    ldx4(bl4, wlb + boff);
                    mma_h(acc[2*np],   ax[ks], bl4[0], bl4[1]);
                    mma_h(acc[2*np],   al[ks], bh4[0], bh4[1]);
                    mma_h(acc[2*np+1], ax[ks], bl4[2], bl4[3]);
                    mma_h(acc[2*np+1], al[ks], bh4[2], bh4[3]);
                }
            }
        }
    }

    const float* bsec = (sec == 0) ? bq : (sec == 1) ? bk : bv;
    #pragma unroll
    for (int nt = 0; nt < 4; nt++) {
        int ct = 32*wc + 8*nt + 2*t4;
        int c = nbase + ct;
        float b0v = bsec[c], b1v = bsec[c+1];
        #pragma unroll
        for (int rr = 0; rr < 2; rr++) {
            int gm = m0 + 16*wr + g + rr*8;
            if (gm >= MTOT) continue;
            float v0 = acc[nt][2*rr]   + b0v;
            float v1 = acc[nt][2*rr+1] + b1v;
            int b = gm / SS, srow = gm % SS;
            if (sec == 0) {
                *(__half2*)&d_qh[(((size_t)b*HH + (c>>5))*SS + srow)*HD + (c&31)] =
                    __floats2half2_rn(v0, v1);
            } else if (sec == 1) {
                *(__half2*)&d_kh[(((size_t)b*HH + (c>>5))*SS + srow)*HD + (c&31)] =
                    __floats2half2_rn(v0*KSCALE, v1*KSCALE);
            } else {
                *(float2*)&d_v[(size_t)gm*CC + c] = make_float2(v0, v1);
            }
        }
    }
}

// ---------------------------------------------------------------------------
// Kernel 2: fp16 mma.sync attention — 2 heads per block, fp32 accumulators.
// K pre-scaled by SCALE*log2e; packed-fp16 epilogue (R12 winner).
// K tiles double-buffered via cp.async (no register staging).
// ---------------------------------------------------------------------------
__global__ void __launch_bounds__(256, 3) attn_mma_kernel()
{
    __shared__ __align__(16) u16 Qsm[2*64*40];     // 10240 B (2 heads)
    __shared__ __align__(16) u16 Ksm[2*2*64*40];   // 20480 B (2 heads x double buf)

    const int t = threadIdx.x;
    const int w = t >> 5, lane = t & 31;
    const int g = lane >> 2, t4 = lane & 3;
    const int hp = w >> 2, w4 = w & 3;
    const int bhp = blockIdx.x;
    const int b = bhp >> 2, hpair = bhp & 3;
    const int h = hpair*2 + hp;
    const int q0 = blockIdx.y * 64;

    // ---- stage Q tiles for both heads ----
    {
        int hld = t >> 7, r = (t >> 1) & 63, part = t & 1;
        const __half* qb2 = d_qh + (((size_t)b*HH + hpair*2 + hld) * SS) * HD;
        int gq = q0 + r;
        uint4 a0 = make_uint4(0u,0u,0u,0u), a1 = make_uint4(0u,0u,0u,0u);
        if (gq < SS) {
            a0 = *(const uint4*)(qb2 + (size_t)gq*HD + part*16);
            a1 = *(const uint4*)(qb2 + (size_t)gq*HD + part*16 + 8);
        }
        *(uint4*)&Qsm[hld*64*40 + r*40 + part*16]     = a0;
        *(uint4*)&Qsm[hld*64*40 + r*40 + part*16 + 8] = a1;
    }
    __syncthreads();

    u32 qa[2][4];
    {
        u32 qs = smem_u32(Qsm) + (u32)(hp*64*40*2);
        int row = 16*w4 + (lane & 15);
        int cb = (lane >> 4) * 8;
        ldx4(qa[0], qs + (u32)((row*40 + cb) * 2));
        ldx4(qa[1], qs + (u32)((row*40 + cb + 16) * 2));
    }

    const u32 ks_base = smem_u32(Ksm);

    const int r0  = q0 + 16*w4 + g;
    const int r1i = r0 + 8;
    const __half* mbb = d_m16 + (size_t)b * SS * SS;
    const __half* mr0 = (r0  < SS) ? mbb + (size_t)r0  * SS : (const __half*)0;
    const __half* mr1 = (r1i < SS) ? mbb + (size_t)r1i * SS : (const __half*)0;

    float oacc[4][4];
    #pragma unroll
    for (int i = 0; i < 4; i++)
        #pragma unroll
        for (int c = 0; c < 4; c++) oacc[i][c] = 0.f;
    float rs0 = 0.f, rs1 = 0.f;

    // mask prefetch double-buffer (f16x2 pairs)
    u32 mbuf[2][4];
    auto do_pref = [&](int gjdx, u32* dst) {
        int base = gjdx * 16;
        #pragma unroll
        for (int p = 0; p < 2; p++) {
            int gk = base + p*8 + 2*t4;
            u32 v0 = 0u, v1 = 0u;
            if (gk < SS) {
                if (mr0) v0 = *(const u32*)(mr0 + gk);
                if (mr1) v1 = *(const u32*)(mr1 + gk);
            }
            dst[2*p]   = v0;
            dst[2*p+1] = v1;
        }
    };
    do_pref(0, mbuf[0]);

    // K tile cp.async: 256 thr cover 2 heads x 64 rows x 2 16B-chunks
    const int khld = t >> 7, kkr = (t >> 1) & 63, kpart = t & 1;
    const __half* kldb = d_kh + (((size_t)b*HH + hpair*2 + khld) * SS) * HD;
    auto ldK_async = [&](int kt, int buf) {
        int gk = kt*64 + kkr;
        u32 sz = (gk < SS) ? 16u : 0u;
        int gc = (gk < SS) ? gk : (SS - 1);
        const __half* src = kldb + (size_t)gc*HD + kpart*16;
        u32 dst = ks_base + (u32)((((khld*2 + buf)*64 + kkr)*40 + kpart*16) * 2);
        cp16(dst,      src,     sz);
        cp16(dst + 16, src + 8, sz);
    };

    ldK_async(0, 0);
    CP_COMMIT();
    CP_WAIT0();
    __syncthreads();

    for (int kt = 0; kt < NKT2; kt++) {
        const u32 ks = ks_base + (u32)(((hp*2 + (kt & 1)) * 64*40) * 2);
        // issue next tile (tail over-issues with zero-fill; harmless)
        ldK_async(kt + 1, (kt + 1) & 1);
        CP_COMMIT();

        u32 rsh0 = 0u, rsh1 = 0u;         // per-tile f16x2 rowsum

        #pragma unroll
        for (int j = 0; j < 4; j++) {
            const u32* mc = mbuf[j & 1];
            // ---- QK (fp32 acc) ----
            float sc[2][4];
            #pragma unroll
            for (int p = 0; p < 2; p++) {
                #pragma unroll
                for (int c = 0; c < 4; c++) sc[p][c] = 0.f;
                int nt = 2*j + p;
                u32 br[4];
                ldx4(br, ks + (u32)(((nt*8 + (lane & 7))*40 + ((lane>>3)&3)*8) * 2));
                mma_h(sc[p], qa[0], br[0], br[1]);
                mma_h(sc[p], qa[1], br[2], br[3]);
            }
            // prefetch next chunk's mask
            {
                int gn = kt*4 + j + 1;
                if (gn < NKT2*4) do_pref(gn, mbuf[(j+1) & 1]);
            }
            // ---- epilogue (packed fp16): w = m16 * 2^s ----
            u32 wh[4];
            #pragma unroll
            for (int p = 0; p < 2; p++) {
                u32 s01 = pack_h2(sc[p][0], sc[p][1]);
                u32 s23 = pack_h2(sc[p][2], sc[p][3]);
                u32 w0 = hmul2u(mc[2*p],   ex2h2(s01));
                u32 w1 = hmul2u(mc[2*p+1], ex2h2(s23));
                rsh0 = hadd2u(rsh0, w0);
                rsh1 = hadd2u(rsh1, w1);
                wh[2*p]   = w0;
                wh[2*p+1] = w1;
            }
            // ---- PV via trans-ldmatrix straight from K tile ----
            #pragma unroll
            for (int ip = 0; ip < 2; ip++) {
                u32 vr[4];
                ldx4t(vr, ks + (u32)(((16*j + ((lane>>3)&1)*8 + (lane & 7))*40
                                      + ((lane>>4)&1)*8 + ip*16) * 2));
                mma_h(oacc[2*ip],   wh, vr[0], vr[1]);
                mma_h(oacc[2*ip+1], wh, vr[2], vr[3]);
            }
        }

        // flush per-tile rowsum to f32
        {
            float2 f0 = __half22float2(*reinterpret_cast<__half2*>(&rsh0));
            float2 f1 = __half22float2(*reinterpret_cast<__half2*>(&rsh1));
            rs0 += f0.x + f0.y;
            rs1 += f1.x + f1.y;
        }

        CP_WAIT0();
        __syncthreads();
    }

    rs0 += __shfl_xor_sync(0xffffffffu, rs0, 1);
    rs0 += __shfl_xor_sync(0xffffffffu, rs0, 2);
    rs1 += __shfl_xor_sync(0xffffffffu, rs1, 1);
    rs1 += __shfl_xor_sync(0xffffffffu, rs1, 2);
    // V carried an extra log2(e) factor (K==V storage); ln2 compensates exactly.
    float inv0 = LN2 / rs0;
    float inv1 = LN2 / rs1;

    if (r0 < SS) {
        float* o = d_acc + ((size_t)b*SS + r0)*CC + h*HD + 2*t4;
        #pragma unroll
        for (int i = 0; i < 4; i++)
            *(float2*)(o + i*8) = make_float2(oacc[i][0]*inv0, oacc[i][1]*inv0);
    }
    if (r1i < SS) {
        float* o = d_acc + ((size_t)b*SS + r1i)*CC + h*HD + 2*t4;
        #pragma unroll
        for (int i = 0; i < 4; i++)
            *(float2*)(o + i*8) = make_float2(oacc[i][2]*inv1, oacc[i][3]*inv1);
    }
}

// ---------------------------------------------------------------------------
// Kernel 3: LEPE depthwise 5x5 conv + acc split to fp16 hi/lo.
// Interior positions (52x52) take a fully-unrolled branch-free path.
// ---------------------------------------------------------------------------
__global__ __launch_bounds__(256) void lepe_kernel(
    const float* __restrict__ lw, const float* __restrict__ lb)
{
    int blk = blockIdx.x;
    int b = blk / SS, srow = blk % SS;
    int c = threadIdx.x;
    size_t idx = ((size_t)b*SS + srow)*CC + c;
    float a = d_acc[idx];
    if (srow >= QN) {
        int p = srow - QN;
        int y = p / 56, x = p % 56;
        float l = lb[c];
        if (y >= 2 && y < 54 && x >= 2 && x < 54) {
            const float* vp = d_v + ((size_t)b*SS + QN + (y-2)*56 + (x-2))*CC + c;
            const float* wp = lw + c;
            #pragma unroll
            for (int ky = 0; ky < 5; ky++)
                #pragma unroll
                for (int kx = 0; kx < 5; kx++)
                    l += vp[(size_t)(ky*56 + kx)*CC] * wp[(size_t)(ky*5 + kx)*CC];
        } else {
            #pragma unroll
            for (int ky = 0; ky < 5; ky++) {
                int iy = y + ky - 2;
                if (iy < 0 || iy >= 56) continue;
                #pragma unroll
                for (int kx = 0; kx < 5; kx++) {
                    int ix = x + kx - 2;
                    if (ix < 0 || ix >= 56) continue;
                    l += d_v[((size_t)b*SS + QN + iy*56 + ix)*CC + c] * lw[(ky*5 + kx)*CC + c];
                }
            }
        }
        a += l;
    }
    __half h, lo; split_h(a, h, lo);
    d_acch[idx] = h;
    d_accl[idx] = lo;
}

// ---------------------------------------------------------------------------
// Kernel 4: output projection, split-fp16 HMMA (3-pass). 64x64 tiles.
// ---------------------------------------------------------------------------
__global__ __launch_bounds__(256) void out_kernel(
    const float* __restrict__ bo, float* __restrict__ out)
{
    __shared__ __align__(16) u16 Xh[64*40];
    __shared__ __align__(16) u16 Xl[64*40];
    __shared__ __align__(16) u16 Wh[64*40];
    __shared__ __align__(16) u16 Wl[64*40];

    const int m0 = blockIdx.x * 64;
    const int n0 = blockIdx.y * 64;
    const int t = threadIdx.x;
    const int w = t >> 5, lane = t & 31;
    const int g = lane >> 2, t4 = lane & 3;
    const int wr = w >> 1, wc = w & 1;

    float acc[4][4];
    #pragma unroll
    for (int i = 0; i < 4; i++)
        #pragma unroll
        for (int c = 0; c < 4; c++) acc[i][c] = 0.f;

    const u32 xb  = smem_u32(Xh), xlb = smem_u32(Xl);
    const u32 wb  = smem_u32(Wh), wlb = smem_u32(Wl);

    for (int kk = 0; kk < CC; kk += 32) {
        __syncthreads();
        {
            int r = t >> 2, c8 = (t & 3) * 8;
            int gm = m0 + r;
            uint4 a = make_uint4(0u,0u,0u,0u), bvv = make_uint4(0u,0u,0u,0u);
            if (gm < MTOT) {
                a   = *(const uint4*)&d_acch[(size_t)gm*CC + kk + c8];
                bvv = *(const uint4*)&d_accl[(size_t)gm*CC + kk + c8];
            }
            *(uint4*)&Xh[r*40 + c8] = a;
            *(uint4*)&Xl[r*40 + c8] = bvv;
            int wrow = n0 + r;
            *(uint4*)&Wh[r*40 + c8] = *(const uint4*)&d_woh[(size_t)wrow*CC + kk + c8];
            *(uint4*)&Wl[r*40 + c8] = *(const uint4*)&d_wol[(size_t)wrow*CC + kk + c8];
        }
        __syncthreads();

        u32 ax[2][4], al[2][4];
        #pragma unroll
        for (int ks = 0; ks < 2; ks++) {
            u32 aoff = (u32)(((16*wr + (lane & 15))*40 + ks*16 + ((lane>>4)&1)*8) * 2);
            ldx4(ax[ks], xb  + aoff);
            ldx4(al[ks], xlb + aoff);
        }
        #pragma unroll
        for (int ks = 0; ks < 2; ks++) {
            #pragma unroll
            for (int np = 0; np < 2; np++) {
                u32 boff = (u32)(((32*wc + np*16 + ((lane>>4)&1)*8 + (lane & 7))*40
                                  + ks*16 + ((lane>>3)&1)*8) * 2);
                u32 bh4[4], bl4[4];
                ldx4(bh4, wb  + boff);
                ldx4(bl4, wlb + boff);
                mma_h(acc[2*np],   ax[ks], bh4[0], bh4[1]);
                mma_h(acc[2*np],   ax[ks], bl4[0], bl4[1]);
                mma_h(acc[2*np],   al[ks], bh4[0], bh4[1]);
                mma_h(acc[2*np+1], ax[ks], bh4[2], bh4[3]);
                mma_h(acc[2*np+1], ax[ks], bl4[2], bl4[3]);
                mma_h(acc[2*np+1], al[ks], bh4[2], bh4[3]);
            }
        }
    }

    #pragma unroll
    for (int nt = 0; nt < 4; nt++) {
        int n = n0 + 32*wc + 8*nt + 2*t4;
        float b0v = bo[n], b1v = bo[n+1];
        #pragma unroll
        for (int rr = 0; rr < 2; rr++) {
            int gm = m0 + 16*wr + g + rr*8;
            if (gm >= MTOT) continue;
            *(float2*)&out[(size_t)gm*CC + n] =
                make_float2(acc[nt][2*rr] + b0v, acc[nt][2*rr+1] + b1v);
        }
    }
}

// ---------------------------------------------------------------------------
extern "C" void kernel_launch(void* const* d_in, const int* in_sizes, int n_in,
                              void* d_out, int out_size) {
    const float* x    = (const float*)d_in[0];
    const float* mask = (const float*)d_in[1];
    const float* wq   = (const float*)d_in[2];
    const float* bq   = (const float*)d_in[3];
    const float* wk   = (const float*)d_in[4];
    const float* bk   = (const float*)d_in[5];
    const float* wv   = (const float*)d_in[6];
    const float* bv   = (const float*)d_in[7];
    const float* lw   = (const float*)d_in[8];
    const float* lb   = (const float*)d_in[9];
    const float* wo   = (const float*)d_in[10];
    const float* bo   = (const float*)d_in[11];
    float* out = (float*)d_out;

    cvt_kernel<<<1024, 256>>>(wq, wk, wv, wo);
    mask16_kernel<<<(int)((NM/8 + 255)/256), 256>>>(mask);
    dim3 g1(99, 12);
    qkv_kernel<<<g1, 256>>>(x, bq, bk, bv);
    dim3 g2(BB*4, NQT64);
    attn_mma_kernel<<<g2, 256>>>();
    lepe_kernel<<<BB*SS, 256>>>(lw, lb);
    dim3 g4(99, 4);
    out_kernel<<<g4, 256>>>(bo, out);
}

// round 15
// speedup vs baseline: 1.2521x; 1.0097x over previous
#include <cuda_runtime.h>
#include <cuda_fp16.h>
#include <cstdint>

#define BB 2
#define SS 3144
#define CC 256
#define HH 8
#define HD 32
#define QN 8
#define MTOT (BB*SS)            /* 6288 */
#define SCALE 0.1767766952966369f
#define KSCALE (0.1767766952966369f * 1.44269504f)   /* SCALE * log2(e) */
#define LN2 0.6931471805599453f
#define NKT2 ((SS + 63) / 64)   /* 50 key tiles of 64 */
#define NQT64 ((SS + 63) / 64)  /* 50 query tiles of 64 */
#define NM ((size_t)BB*SS*SS)

typedef unsigned long long u64;
typedef unsigned int u32;
typedef unsigned short u16;

__device__ __align__(16) __half d_qh[BB*HH*SS*HD];  // head-major fp16
__device__ __align__(16) __half d_kh[BB*HH*SS*HD];  // scaled by KSCALE (K and V)
__device__ __align__(16) float  d_v[BB*SS*CC];
__device__ __align__(16) float  d_acc[BB*SS*CC];    // attention out (f32)
__device__ __align__(16) __half d_m16[BB*SS*SS];    // (mask + 1e-6) in fp16
__device__ __align__(16) __half d_wh[768*CC];       // [wq;wk;wv] split
__device__ __align__(16) __half d_wl[768*CC];
__device__ __align__(16) __half d_woh[CC*CC];       // wo split
__device__ __align__(16) __half d_wol[CC*CC];
__device__ __align__(16) __half d_acch[BB*SS*CC];   // acc(+lepe) split
__device__ __align__(16) __half d_accl[BB*SS*CC];

// ---------------- helpers ----------------
__device__ __forceinline__ u32 smem_u32(const void* p) {
    u32 a;
    asm("{ .reg .u64 t; cvta.to.shared.u64 t, %1; cvt.u32.u64 %0, t; }" : "=r"(a) : "l"(p));
    return a;
}
__device__ __forceinline__ u32 pack_h2(float lo, float hi) {
    u32 r; asm("cvt.rn.f16x2.f32 %0, %1, %2;" : "=r"(r) : "f"(hi), "f"(lo)); return r;
}
__device__ __forceinline__ u32 ex2h2(u32 x) {
    u32 r; asm("ex2.approx.f16x2 %0, %1;" : "=r"(r) : "r"(x)); return r;
}
__device__ __forceinline__ u32 hmul2u(u32 a, u32 b) {
    u32 r; asm("mul.rn.f16x2 %0, %1, %2;" : "=r"(r) : "r"(a), "r"(b)); return r;
}
__device__ __forceinline__ u32 hadd2u(u32 a, u32 b) {
    u32 r; asm("add.rn.f16x2 %0, %1, %2;" : "=r"(r) : "r"(a), "r"(b)); return r;
}
__device__ __forceinline__ void fma2(u64 &d, u64 a, u64 b) {
    asm("fma.rn.f32x2 %0, %1, %2, %0;" : "+l"(d) : "l"(a), "l"(b));
}
__device__ __forceinline__ float2 unpack2(u64 v) {
    float2 r; asm("mov.b64 {%0, %1}, %2;" : "=f"(r.x), "=f"(r.y) : "l"(v)); return r;
}
__device__ __forceinline__ void ldx4(u32* r, u32 saddr) {
    asm volatile("ldmatrix.sync.aligned.m8n8.x4.shared.b16 {%0,%1,%2,%3}, [%4];"
                 : "=r"(r[0]), "=r"(r[1]), "=r"(r[2]), "=r"(r[3]) : "r"(saddr));
}
__device__ __forceinline__ void ldx4t(u32* r, u32 saddr) {
    asm volatile("ldmatrix.sync.aligned.m8n8.x4.trans.shared.b16 {%0,%1,%2,%3}, [%4];"
                 : "=r"(r[0]), "=r"(r[1]), "=r"(r[2]), "=r"(r[3]) : "r"(saddr));
}
__device__ __forceinline__ void mma_h(float* c, const u32* a, u32 b0, u32 b1) {
    asm volatile("mma.sync.aligned.m16n8k16.row.col.f32.f16.f16.f32 "
                 "{%0,%1,%2,%3}, {%4,%5,%6,%7}, {%8,%9}, {%0,%1,%2,%3};"
                 : "+f"(c[0]), "+f"(c[1]), "+f"(c[2]), "+f"(c[3])
                 : "r"(a[0]), "r"(a[1]), "r"(a[2]), "r"(a[3]), "r"(b0), "r"(b1));
}
__device__ __forceinline__ void split_h(float v, __half &h, __half &l) {
    h = __float2half_rn(v);
    l = __float2half_rn(v - __half2float(h));
}
__device__ __forceinline__ void cp16(u32 dst, const void* src, u32 sz) {
    asm volatile("cp.async.ca.shared.global [%0], [%1], 16, %2;"
                 :: "r"(dst), "l"(src), "r"(sz));
}
#define CP_COMMIT() asm volatile("cp.async.commit_group;" ::: "memory")
#define CP_WAIT0()  asm volatile("cp.async.wait_group 0;" ::: "memory")

// ---------------------------------------------------------------------------
// Kernel 0a: split [wq;wk;wv], wo into fp16 hi/lo (weights only)
// ---------------------------------------------------------------------------
__global__ __launch_bounds__(256) void cvt_kernel(
    const float* __restrict__ wq, const float* __restrict__ wk,
    const float* __restrict__ wv, const float* __restrict__ wo)
{
    int j = blockIdx.x * 256 + threadIdx.x;      // 0 .. 4*65536-1
    int sec = j >> 16, off = j & 65535;
    const float* src = (sec == 0) ? wq : (sec == 1) ? wk : (sec == 2) ? wv : wo;
    __half h, l; split_h(src[off], h, l);
    if (sec < 3) { d_wh[j] = h; d_wl[j] = l; }
    else         { d_woh[off] = h; d_wol[off] = l; }
}

// ---------------------------------------------------------------------------
// Kernel 0b: mask -> fp16 with +1e-6 folded in
// ---------------------------------------------------------------------------
__global__ __launch_bounds__(256) void mask16_kernel(const float* __restrict__ m)
{
    size_t i = ((size_t)blockIdx.x * 256 + threadIdx.x) * 8;
    if (i >= NM) return;
    float4 a = *(const float4*)(m + i);
    float4 b = *(const float4*)(m + i + 4);
    __half hh[8];
    hh[0] = __float2half_rn(a.x + 1e-6f);
    hh[1] = __float2half_rn(a.y + 1e-6f);
    hh[2] = __float2half_rn(a.z + 1e-6f);
    hh[3] = __float2half_rn(a.w + 1e-6f);
    hh[4] = __float2half_rn(b.x + 1e-6f);
    hh[5] = __float2half_rn(b.y + 1e-6f);
    hh[6] = __float2half_rn(b.z + 1e-6f);
    hh[7] = __float2half_rn(b.w + 1e-6f);
    *(uint4*)&d_m16[i] = *(uint4*)hh;
}

// ---------------------------------------------------------------------------
// Kernel 1: fused QKV projection. x split in-kernel.
// q,k sections: single-pass fp16 HMMA. v section: 3-pass split-fp16.
// ---------------------------------------------------------------------------
__global__ __launch_bounds__(256) void qkv_kernel(
    const float* __restrict__ x,
    const float* __restrict__ bq, const float* __restrict__ bk,
    const float* __restrict__ bv)
{
    __shared__ __align__(16) u16 Xh[64*40];
    __shared__ __align__(16) u16 Xl[64*40];
    __shared__ __align__(16) u16 Wh[64*40];
    __shared__ __align__(16) u16 Wl[64*40];

    const int m0 = blockIdx.x * 64;
    const int n0 = blockIdx.y * 64;       // global 0..767
    const int t = threadIdx.x;
    const int w = t >> 5, lane = t & 31;
    const int g = lane >> 2, t4 = lane & 3;
    const int wr = w >> 1, wc = w & 1;
    const int sec = n0 >> 8;
    const int nbase = n0 & 255;
    const bool isv = (sec == 2);

    float acc[4][4];
    #pragma unroll
    for (int i = 0; i < 4; i++)
        #pragma unroll
        for (int c = 0; c < 4; c++) acc[i][c] = 0.f;

    const u32 xb  = smem_u32(Xh), xlb = smem_u32(Xl);
    const u32 wb  = smem_u32(Wh), wlb = smem_u32(Wl);

    for (int kk = 0; kk < CC; kk += 32) {
        __syncthreads();
        {
            int r = t >> 2, c8 = (t & 3) * 8;
            int gm = m0 + r;
            float4 f0 = make_float4(0.f,0.f,0.f,0.f), f1 = f0;
            if (gm < MTOT) {
                f0 = *(const float4*)(x + (size_t)gm*CC + kk + c8);
                f1 = *(const float4*)(x + (size_t)gm*CC + kk + c8 + 4);
            }
            float vv[8] = {f0.x,f0.y,f0.z,f0.w,f1.x,f1.y,f1.z,f1.w};
            __half hh[8], ll[8];
            #pragma unroll
            for (int i = 0; i < 8; i++) split_h(vv[i], hh[i], ll[i]);
            *(uint4*)&Xh[r*40 + c8] = *(uint4*)hh;
            if (isv) *(uint4*)&Xl[r*40 + c8] = *(uint4*)ll;
            int wrow = n0 + r;
            *(uint4*)&Wh[r*40 + c8] = *(const uint4*)&d_wh[(size_t)wrow*CC + kk + c8];
            if (isv) *(uint4*)&Wl[r*40 + c8] = *(const uint4*)&d_wl[(size_t)wrow*CC + kk + c8];
        }
        __syncthreads();

        u32 ax[2][4], al[2][4];
        #pragma unroll
        for (int ks = 0; ks < 2; ks++) {
            u32 aoff = (u32)(((16*wr + (lane & 15))*40 + ks*16 + ((lane>>4)&1)*8) * 2);
            ldx4(ax[ks], xb + aoff);
            if (isv) ldx4(al[ks], xlb + aoff);
        }
        #pragma unroll
        for (int ks = 0; ks < 2; ks++) {
            #pragma unroll
            for (int np = 0; np < 2; np++) {
                u32 boff = (u32)(((32*wc + np*16 + ((lane>>4)&1)*8 + (lane & 7))*40
                                  + ks*16 + ((lane>>3)&1)*8) * 2);
                u32 bh4[4];
                ldx4(bh4, wb + boff);
                mma_h(acc[2*np],   ax[ks], bh4[0], bh4[1]);
                mma_h(acc[2*np+1], ax[ks], bh4[2], bh4[3]);
                if (isv) {
                    u32 bl4[4];
                    ldx4(bl4, wlb + boff);
                    mma_h(acc[2*np],   ax[ks], bl4[0], bl4[1]);
                    mma_h(acc[2*np],   al[ks], bh4[0], bh4[1]);
                    mma_h(acc[2*np+1], ax[ks], bl4[2], bl4[3]);
                    mma_h(acc[2*np+1], al[ks], bh4[2], bh4[3]);
                }
            }
        }
    }

    const float* bsec = (sec == 0) ? bq : (sec == 1) ? bk : bv;
    #pragma unroll
    for (int nt = 0; nt < 4; nt++) {
        int ct = 32*wc + 8*nt + 2*t4;
        int c = nbase + ct;
        float b0v = bsec[c], b1v = bsec[c+1];
        #pragma unroll
        for (int rr = 0; rr < 2; rr++) {
            int gm = m0 + 16*wr + g + rr*8;
            if (gm >= MTOT) continue;
            float v0 = acc[nt][2*rr]   + b0v;
            float v1 = acc[nt][2*rr+1] + b1v;
            int b = gm / SS, srow = gm % SS;
            if (sec == 0) {
                *(__half2*)&d_qh[(((size_t)b*HH + (c>>5))*SS + srow)*HD + (c&31)] =
                    __floats2half2_rn(v0, v1);
            } else if (sec == 1) {
                *(__half2*)&d_kh[(((size_t)b*HH + (c>>5))*SS + srow)*HD + (c&31)] =
                    __floats2half2_rn(v0*KSCALE, v1*KSCALE);
            } else {
                *(float2*)&d_v[(size_t)gm*CC + c] = make_float2(v0, v1);
            }
        }
    }
}

// ---------------------------------------------------------------------------
// Kernel 2: fp16 mma.sync attention — 2 heads per block, fp32 accumulators.
// Packed-fp16 epilogue; cp.async K pipeline; 2 k-tiles per sync (4-deep ring).
// ---------------------------------------------------------------------------
__global__ void __launch_bounds__(256, 3) attn_mma_kernel()
{
    __shared__ __align__(16) u16 Qsm[2*64*40];       // 10240 B (2 heads)
    __shared__ __align__(16) u16 Ksm[2*4*64*40];     // 40960 B (2 heads x 4 bufs)

    const int t = threadIdx.x;
    const int w = t >> 5, lane = t & 31;
    const int g = lane >> 2, t4 = lane & 3;
    const int hp = w >> 2, w4 = w & 3;
    const int bhp = blockIdx.x;
    const int b = bhp >> 2, hpair = bhp & 3;
    const int h = hpair*2 + hp;
    const int q0 = blockIdx.y * 64;

    // ---- stage Q tiles for both heads ----
    {
        int hld = t >> 7, r = (t >> 1) & 63, part = t & 1;
        const __half* qb2 = d_qh + (((size_t)b*HH + hpair*2 + hld) * SS) * HD;
        int gq = q0 + r;
        uint4 a0 = make_uint4(0u,0u,0u,0u), a1 = make_uint4(0u,0u,0u,0u);
        if (gq < SS) {
            a0 = *(const uint4*)(qb2 + (size_t)gq*HD + part*16);
            a1 = *(const uint4*)(qb2 + (size_t)gq*HD + part*16 + 8);
        }
        *(uint4*)&Qsm[hld*64*40 + r*40 + part*16]     = a0;
        *(uint4*)&Qsm[hld*64*40 + r*40 + part*16 + 8] = a1;
    }
    __syncthreads();

    u32 qa[2][4];
    {
        u32 qs = smem_u32(Qsm) + (u32)(hp*64*40*2);
        int row = 16*w4 + (lane & 15);
        int cb = (lane >> 4) * 8;
        ldx4(qa[0], qs + (u32)((row*40 + cb) * 2));
        ldx4(qa[1], qs + (u32)((row*40 + cb + 16) * 2));
    }

    const u32 ks_base = smem_u32(Ksm);

    const int r0  = q0 + 16*w4 + g;
    const int r1i = r0 + 8;
    const __half* mbb = d_m16 + (size_t)b * SS * SS;
    const __half* mr0 = (r0  < SS) ? mbb + (size_t)r0  * SS : (const __half*)0;
    const __half* mr1 = (r1i < SS) ? mbb + (size_t)r1i * SS : (const __half*)0;

    float oacc[4][4];
    #pragma unroll
    for (int i = 0; i < 4; i++)
        #pragma unroll
        for (int c = 0; c < 4; c++) oacc[i][c] = 0.f;
    float rs0 = 0.f, rs1 = 0.f;

    // mask prefetch double-buffer (f16x2 pairs)
    u32 mbuf[2][4];
    auto do_pref = [&](int gjdx, u32* dst) {
        int base = gjdx * 16;
        #pragma unroll
        for (int p = 0; p < 2; p++) {
            int gk = base + p*8 + 2*t4;
            u32 v0 = 0u, v1 = 0u;
            if (gk < SS) {
                if (mr0) v0 = *(const u32*)(mr0 + gk);
                if (mr1) v1 = *(const u32*)(mr1 + gk);
            }
            dst[2*p]   = v0;
            dst[2*p+1] = v1;
        }
    };
    do_pref(0, mbuf[0]);

    // K tile cp.async: 256 thr cover 2 heads x 64 rows x 2 16B-chunks
    const int khld = t >> 7, kkr = (t >> 1) & 63, kpart = t & 1;
    const __half* kldb = d_kh + (((size_t)b*HH + hpair*2 + khld) * SS) * HD;
    auto ldK_async = [&](int kt, int buf) {
        int gk = kt*64 + kkr;
        u32 sz = (gk < SS) ? 16u : 0u;
        int gc = (gk < SS) ? gk : (SS - 1);
        const __half* src = kldb + (size_t)gc*HD + kpart*16;
        u32 dst = ks_base + (u32)((((khld*4 + buf)*64 + kkr)*40 + kpart*16) * 2);
        cp16(dst,      src,     sz);
        cp16(dst + 16, src + 8, sz);
    };

    ldK_async(0, 0);
    ldK_async(1, 1);
    CP_COMMIT();
    CP_WAIT0();
    __syncthreads();

    for (int it = 0; it < NKT2/2; it++) {
        const int kt0 = it*2;
        // issue next two tiles (tail over-issues with zero-fill; harmless)
        ldK_async(kt0 + 2, (kt0 + 2) & 3);
        ldK_async(kt0 + 3, (kt0 + 3) & 3);
        CP_COMMIT();

        u32 rsh0 = 0u, rsh1 = 0u;         // per-2-tile f16x2 rowsum

        #pragma unroll
        for (int sub = 0; sub < 2; sub++) {
            const int kt = kt0 + sub;
            const u32 ks = ks_base + (u32)(((hp*4 + (kt & 3)) * 64*40) * 2);

            #pragma unroll
            for (int j = 0; j < 4; j++) {
                const u32* mc = mbuf[j & 1];
                // ---- QK (fp32 acc) ----
                float sc[2][4];
                #pragma unroll
                for (int p = 0; p < 2; p++) {
                    #pragma unroll
                    for (int c = 0; c < 4; c++) sc[p][c] = 0.f;
                    int nt = 2*j + p;
                    u32 br[4];
                    ldx4(br, ks + (u32)(((nt*8 + (lane & 7))*40 + ((lane>>3)&3)*8) * 2));
                    mma_h(sc[p], qa[0], br[0], br[1]);
                    mma_h(sc[p], qa[1], br[2], br[3]);
                }
                // prefetch next chunk's mask
                {
                    int gn = kt*4 + j + 1;
                    if (gn < NKT2*4) do_pref(gn, mbuf[(j+1) & 1]);
                }
                // ---- epilogue (packed fp16): w = m16 * 2^s ----
                u32 wh[4];
                #pragma unroll
                for (int p = 0; p < 2; p++) {
                    u32 s01 = pack_h2(sc[p][0], sc[p][1]);
                    u32 s23 = pack_h2(sc[p][2], sc[p][3]);
                    u32 w0 = hmul2u(mc[2*p],   ex2h2(s01));
                    u32 w1 = hmul2u(mc[2*p+1], ex2h2(s23));
                    rsh0 = hadd2u(rsh0, w0);
                    rsh1 = hadd2u(rsh1, w1);
                    wh[2*p]   = w0;
                    wh[2*p+1] = w1;
                }
                // ---- PV via trans-ldmatrix straight from K tile ----
                #pragma unroll
                for (int ip = 0; ip < 2; ip++) {
                    u32 vr[4];
                    ldx4t(vr, ks + (u32)(((16*j + ((lane>>3)&1)*8 + (lane & 7))*40
                                          + ((lane>>4)&1)*8 + ip*16) * 2));
                    mma_h(oacc[2*ip],   wh, vr[0], vr[1]);
                    mma_h(oacc[2*ip+1], wh, vr[2], vr[3]);
                }
            }
        }

        // flush per-2-tile rowsum to f32
        {
            float2 f0 = __half22float2(*reinterpret_cast<__half2*>(&rsh0));
            float2 f1 = __half22float2(*reinterpret_cast<__half2*>(&rsh1));
            rs0 += f0.x + f0.y;
            rs1 += f1.x + f1.y;
        }

        CP_WAIT0();
        __syncthreads();
    }

    rs0 += __shfl_xor_sync(0xffffffffu, rs0, 1);
    rs0 += __shfl_xor_sync(0xffffffffu, rs0, 2);
    rs1 += __shfl_xor_sync(0xffffffffu, rs1, 1);
    rs1 += __shfl_xor_sync(0xffffffffu, rs1, 2);
    // V carried an extra log2(e) factor (K==V storage); ln2 compensates exactly.
    float inv0 = LN2 / rs0;
    float inv1 = LN2 / rs1;

    if (r0 < SS) {
        float* o = d_acc + ((size_t)b*SS + r0)*CC + h*HD + 2*t4;
        #pragma unroll
        for (int i = 0; i < 4; i++)
            *(float2*)(o + i*8) = make_float2(oacc[i][0]*inv0, oacc[i][1]*inv0);
    }
    if (r1i < SS) {
        float* o = d_acc + ((size_t)b*SS + r1i)*CC + h*HD + 2*t4;
        #pragma unroll
        for (int i = 0; i < 4; i++)
            *(float2*)(o + i*8) = make_float2(oacc[i][2]*inv1, oacc[i][3]*inv1);
    }
}

// ---------------------------------------------------------------------------
// Kernel 3: LEPE depthwise 5x5 conv (f32x2: 128 thr, 2 channels/thread)
// + acc split to fp16 hi/lo. Interior branch-free fast path.
// ---------------------------------------------------------------------------
__global__ __launch_bounds__(128) void lepe_kernel(
    const float* __restrict__ lw, const float* __restrict__ lb)
{
    int blk = blockIdx.x;
    int b = blk / SS, srow = blk % SS;
    int c = threadIdx.x * 2;
    size_t idx = ((size_t)b*SS + srow)*CC + c;
    u64 a2 = *(const u64*)&d_acc[idx];
    float2 av = unpack2(a2);
    if (srow >= QN) {
        int p = srow - QN;
        int y = p / 56, x = p % 56;
        u64 l2 = *(const u64*)&lb[c];
        if (y >= 2 && y < 54 && x >= 2 && x < 54) {
            const float* vp = d_v + ((size_t)b*SS + QN + (y-2)*56 + (x-2))*CC + c;
            const float* wp = lw + c;
            #pragma unroll
            for (int ky = 0; ky < 5; ky++)
                #pragma unroll
                for (int kx = 0; kx < 5; kx++)
                    fma2(l2, *(const u64*)(vp + (size_t)(ky*56 + kx)*CC),
                             *(const u64*)(wp + (size_t)(ky*5 + kx)*CC));
        } else {
            #pragma unroll
            for (int ky = 0; ky < 5; ky++) {
                int iy = y + ky - 2;
                if (iy < 0 || iy >= 56) continue;
                #pragma unroll
                for (int kx = 0; kx < 5; kx++) {
                    int ix = x + kx - 2;
                    if (ix < 0 || ix >= 56) continue;
                    fma2(l2, *(const u64*)&d_v[((size_t)b*SS + QN + iy*56 + ix)*CC + c],
                             *(const u64*)&lw[(ky*5 + kx)*CC + c]);
                }
            }
        }
        float2 lv = unpack2(l2);
        av.x += lv.x;
        av.y += lv.y;
    }
    __half h0, l0, h1, l1;
    split_h(av.x, h0, l0);
    split_h(av.y, h1, l1);
    *(__half2*)&d_acch[idx] = __halves2half2(h0, h1);
    *(__half2*)&d_accl[idx] = __halves2half2(l0, l1);
}

// ---------------------------------------------------------------------------
// Kernel 4: output projection, split-fp16 HMMA (3-pass). 64x64 tiles.
// ---------------------------------------------------------------------------
__global__ __launch_bounds__(256) void out_kernel(
    const float* __restrict__ bo, float* __restrict__ out)
{
    __shared__ __align__(16) u16 Xh[64*40];
    __shared__ __align__(16) u16 Xl[64*40];
    __shared__ __align__(16) u16 Wh[64*40];
    __shared__ __align__(16) u16 Wl[64*40];

    const int m0 = blockIdx.x * 64;
    const int n0 = blockIdx.y * 64;
    const int t = threadIdx.x;
    const int w = t >> 5, lane = t & 31;
    const int g = lane >> 2, t4 = lane & 3;
    const int wr = w >> 1, wc = w & 1;

    float acc[4][4];
    #pragma unroll
    for (int i = 0; i < 4; i++)
        #pragma unroll
        for (int c = 0; c < 4; c++) acc[i][c] = 0.f;

    const u32 xb  = smem_u32(Xh), xlb = smem_u32(Xl);
    const u32 wb  = smem_u32(Wh), wlb = smem_u32(Wl);

    for (int kk = 0; kk < CC; kk += 32) {
        __syncthreads();
        {
            int r = t >> 2, c8 = (t & 3) * 8;
            int gm = m0 + r;
            uint4 a = make_uint4(0u,0u,0u,0u), bvv = make_uint4(0u,0u,0u,0u);
            if (gm < MTOT) {
                a   = *(const uint4*)&d_acch[(size_t)gm*CC + kk + c8];
                bvv = *(const uint4*)&d_accl[(size_t)gm*CC + kk + c8];
            }
            *(uint4*)&Xh[r*40 + c8] = a;
            *(uint4*)&Xl[r*40 + c8] = bvv;
            int wrow = n0 + r;
            *(uint4*)&Wh[r*40 + c8] = *(const uint4*)&d_woh[(size_t)wrow*CC + kk + c8];
            *(uint4*)&Wl[r*40 + c8] = *(const uint4*)&d_wol[(size_t)wrow*CC + kk + c8];
        }
        __syncthreads();

        u32 ax[2][4], al[2][4];
        #pragma unroll
        for (int ks = 0; ks < 2; ks++) {
            u32 aoff = (u32)(((16*wr + (lane & 15))*40 + ks*16 + ((lane>>4)&1)*8) * 2);
            ldx4(ax[ks], xb  + aoff);
            ldx4(al[ks], xlb + aoff);
        }
        #pragma unroll
        for (int ks = 0; ks < 2; ks++) {
            #pragma unroll
            for (int np = 0; np < 2; np++) {
                u32 boff = (u32)(((32*wc + np*16 + ((lane>>4)&1)*8 + (lane & 7))*40
                                  + ks*16 + ((lane>>3)&1)*8) * 2);
                u32 bh4[4], bl4[4];
                ldx4(bh4, wb  + boff);
                ldx4(bl4, wlb + boff);
                mma_h(acc[2*np],   ax[ks], bh4[0], bh4[1]);
                mma_h(acc[2*np],   ax[ks], bl4[0], bl4[1]);
                mma_h(acc[2*np],   al[ks], bh4[0], bh4[1]);
                mma_h(acc[2*np+1], ax[ks], bh4[2], bh4[3]);
                mma_h(acc[2*np+1], ax[ks], bl4[2], bl4[3]);
                mma_h(acc[2*np+1], al[ks], bh4[2], bh4[3]);
            }
        }
    }

    #pragma unroll
    for (int nt = 0; nt < 4; nt++) {
        int n = n0 + 32*wc + 8*nt + 2*t4;
        float b0v = bo[n], b1v = bo[n+1];
        #pragma unroll
        for (int rr = 0; rr < 2; rr++) {
            int gm = m0 + 16*wr + g + rr*8;
            if (gm >= MTOT) continue;
            *(float2*)&out[(size_t)gm*CC + n] =
                make_float2(acc[nt][2*rr] + b0v, acc[nt][2*rr+1] + b1v);
        }
    }
}

// ---------------------------------------------------------------------------
extern "C" void kernel_launch(void* const* d_in, const int* in_sizes, int n_in,
                              void* d_out, int out_size) {
    const float* x    = (const float*)d_in[0];
    const float* mask = (const float*)d_in[1];
    const float* wq   = (const float*)d_in[2];
    const float* bq   = (const float*)d_in[3];
    const float* wk   = (const float*)d_in[4];
    const float* bk   = (const float*)d_in[5];
    const float* wv   = (const float*)d_in[6];
    const float* bv   = (const float*)d_in[7];
    const float* lw   = (const float*)d_in[8];
    const float* lb   = (const float*)d_in[9];
    const float* wo   = (const float*)d_in[10];
    const float* bo   = (const float*)d_in[11];
    float* out = (float*)d_out;

    cvt_kernel<<<1024, 256>>>(wq, wk, wv, wo);
    mask16_kernel<<<(int)((NM/8 + 255)/256), 256>>>(mask);
    dim3 g1(99, 12);
    qkv_kernel<<<g1, 256>>>(x, bq, bk, bv);
    dim3 g2(BB*4, NQT64);
    attn_mma_kernel<<<g2, 256>>>();
    lepe_kernel<<<BB*SS, 128>>>(lw, lb);
    dim3 g4(99, 4);
    out_kernel<<<g4, 256>>>(bo, out);
}